// round 1
// baseline (speedup 1.0000x reference)
#include <cuda_runtime.h>
#include <math.h>
#include <math_constants.h>

#define DIMN 1024
#define NH   16
#define HD   64
#define TQ   2048
#define KV   2880     // 2048 self + 768 adapter + 64 task
#define BD   2
#define TASK_OFF 2816

// ---------------- scratch (static device globals; no allocation) ----------------
__device__ float g_Qt[BD*NH*HD*TQ];   // [b][h][d][t]
__device__ float g_Kt[BD*NH*HD*KV];   // [b][h][d][k]  (concat: self|adapter|task)
__device__ float g_V [BD*NH*KV*HD];   // [b][h][k][d]
__device__ float g_AO[BD*TQ*DIMN];    // attention output (B,T,D)
__device__ float g_Y [BD*TQ*DIMN];    // post-Wo + residual
__device__ float g_LN[BD*TQ*DIMN];    // post-LN

// ---------------- generic 128x128x8 SGEMM with fused epilogues ----------------
// MODE 0: plain (B,T,D) out; MODE 1: head layout [b][h][k][d]; MODE 2: head-T [b][h][d][t]
template<int MODE, bool ROPE, bool RESID, bool RELU>
__global__ __launch_bounds__(256) void gemm128(
    const float* __restrict__ A, const float* __restrict__ W,
    const float* __restrict__ bias, const float* __restrict__ resid,
    float* __restrict__ out, int M, int T_A, int Lout, int toff)
{
    __shared__ float As[2][8][128];
    __shared__ float Ws[2][8][128];
    const int tid = threadIdx.x;
    const int tx = tid & 15, ty = tid >> 4;
    const int m0 = blockIdx.y * 128, n0 = blockIdx.x * 128;

    const int arow = tid >> 1, akq = (tid & 1) * 4;
    const int wkrow = tid >> 5, wnq = (tid & 31) * 4;
    const float* Ap = A + (size_t)(m0 + arow) * DIMN + akq;
    const float* Wp = W + (size_t)wkrow * DIMN + n0 + wnq;

    float4 ar = *(const float4*)Ap;
    float4 wr = *(const float4*)Wp;
    As[0][akq+0][arow] = ar.x; As[0][akq+1][arow] = ar.y;
    As[0][akq+2][arow] = ar.z; As[0][akq+3][arow] = ar.w;
    *(float4*)&Ws[0][wkrow][wnq] = wr;
    __syncthreads();

    float acc[8][8];
    #pragma unroll
    for (int i = 0; i < 8; i++)
        #pragma unroll
        for (int j = 0; j < 8; j++) acc[i][j] = 0.0f;

    const int NKT = DIMN / 8;  // 128
    for (int kt = 0; kt < NKT; kt++) {
        const int cur = kt & 1;
        if (kt + 1 < NKT) {
            ar = *(const float4*)(Ap + (size_t)(kt+1)*8);
            wr = *(const float4*)(Wp + (size_t)(kt+1)*8*DIMN);
        }
        #pragma unroll
        for (int kk = 0; kk < 8; kk++) {
            float a[8], b[8];
            *(float4*)&a[0] = *(float4*)&As[cur][kk][ty*4];
            *(float4*)&a[4] = *(float4*)&As[cur][kk][64 + ty*4];
            *(float4*)&b[0] = *(float4*)&Ws[cur][kk][tx*4];
            *(float4*)&b[4] = *(float4*)&Ws[cur][kk][64 + tx*4];
            #pragma unroll
            for (int i = 0; i < 8; i++)
                #pragma unroll
                for (int j = 0; j < 8; j++)
                    acc[i][j] = fmaf(a[i], b[j], acc[i][j]);
        }
        if (kt + 1 < NKT) {
            const int nxt = cur ^ 1;
            As[nxt][akq+0][arow] = ar.x; As[nxt][akq+1][arow] = ar.y;
            As[nxt][akq+2][arow] = ar.z; As[nxt][akq+3][arow] = ar.w;
            *(float4*)&Ws[nxt][wkrow][wnq] = wr;
        }
        __syncthreads();
    }

    // ---- epilogue: bias (+ RoPE) in registers ----
    const float C1 = 0.28782313662425572f;  // ln(10000)/32
    float inv_e0 = 0.f, inv_o0 = 0.f, inv_e1 = 0.f, inv_o1 = 0.f;
    if (ROPE) {
        const int de = tx * 4;  // (n%64) is gj-independent
        inv_e0 = expf(-(float)((de+0) & 31) * C1);
        inv_o0 = expf(-(float)(((de+0) & 31) + 1) * C1);
        inv_e1 = expf(-(float)((de+2) & 31) * C1);
        inv_o1 = expf(-(float)(((de+2) & 31) + 1) * C1);
    }
    #pragma unroll
    for (int gj = 0; gj < 2; gj++) {
        const int n = n0 + gj*64 + tx*4;
        float bz0 = bias[n+0], bz1 = bias[n+1], bz2 = bias[n+2], bz3 = bias[n+3];
        #pragma unroll
        for (int gi = 0; gi < 2; gi++) {
            #pragma unroll
            for (int ii = 0; ii < 4; ii++) {
                float* v = &acc[gi*4+ii][gj*4];
                v[0] += bz0; v[1] += bz1; v[2] += bz2; v[3] += bz3;
                if (ROPE) {
                    const int m = m0 + gi*64 + ty*4 + ii;
                    const float t = (float)(m % T_A);
                    float se, ce, so, co;
                    sincosf(t * inv_e0, &se, &ce);
                    sincosf(t * inv_o0, &so, &co);
                    float e = v[0], o = v[1];
                    v[0] = e*ce - o*se;
                    v[1] = o*co + e*so;
                    sincosf(t * inv_e1, &se, &ce);
                    sincosf(t * inv_o1, &so, &co);
                    e = v[2]; o = v[3];
                    v[2] = e*ce - o*se;
                    v[3] = o*co + e*so;
                }
            }
        }
    }

    // ---- stores ----
    if (MODE == 0) {
        #pragma unroll
        for (int gi = 0; gi < 2; gi++)
        #pragma unroll
        for (int ii = 0; ii < 4; ii++) {
            const int m = m0 + gi*64 + ty*4 + ii;
            #pragma unroll
            for (int gj = 0; gj < 2; gj++) {
                const int n = n0 + gj*64 + tx*4;
                float4 v = *(float4*)&acc[gi*4+ii][gj*4];
                if (RESID) {
                    float4 rx = *(const float4*)&resid[(size_t)m*DIMN + n];
                    v.x += rx.x; v.y += rx.y; v.z += rx.z; v.w += rx.w;
                }
                if (RELU) {
                    v.x = fmaxf(v.x, 0.f); v.y = fmaxf(v.y, 0.f);
                    v.z = fmaxf(v.z, 0.f); v.w = fmaxf(v.w, 0.f);
                }
                *(float4*)&out[(size_t)m*DIMN + n] = v;
            }
        }
    } else if (MODE == 1) {
        #pragma unroll
        for (int gi = 0; gi < 2; gi++)
        #pragma unroll
        for (int ii = 0; ii < 4; ii++) {
            const int m = m0 + gi*64 + ty*4 + ii;
            const int bb = m / T_A, t = m % T_A;
            #pragma unroll
            for (int gj = 0; gj < 2; gj++) {
                const int n = n0 + gj*64 + tx*4;
                const int h = n >> 6, d = n & 63;
                *(float4*)&out[((size_t)(bb*NH + h)*Lout + toff + t)*HD + d] =
                    *(float4*)&acc[gi*4+ii][gj*4];
            }
        }
    } else {  // MODE 2: transposed head layout, float4 along t
        #pragma unroll
        for (int gj = 0; gj < 2; gj++)
        #pragma unroll
        for (int jj = 0; jj < 4; jj++) {
            const int n = n0 + gj*64 + tx*4 + jj;
            const int h = n >> 6, d = n & 63;
            #pragma unroll
            for (int gi = 0; gi < 2; gi++) {
                const int mb = m0 + gi*64 + ty*4;
                const int bb = mb / T_A, t = mb % T_A;
                float4 v = make_float4(acc[gi*4+0][gj*4+jj], acc[gi*4+1][gj*4+jj],
                                       acc[gi*4+2][gj*4+jj], acc[gi*4+3][gj*4+jj]);
                *(float4*)&out[((size_t)(bb*NH + h)*HD + d)*Lout + toff + t] = v;
            }
        }
    }
}

// ---------------- flash-style attention over concatenated KV ----------------
__global__ __launch_bounds__(256) void attn_kernel(
    const float* __restrict__ Qt, const float* __restrict__ Kt,
    const float* __restrict__ V, const float* __restrict__ gate,
    float* __restrict__ out)
{
    __shared__ float Qs[64][64];   // [d][r]
    __shared__ float KPs[64][64];  // K as [d][c], reused as P [r][c]
    __shared__ float Vs[64][64];   // [c][d]
    const int tid = threadIdx.x, tx = tid & 15, ty = tid >> 4;
    const int qt0 = blockIdx.x * 64;
    const int h = blockIdx.y, b = blockIdx.z;
    const int bh = b * NH + h;
    const float g = tanhf(gate[0]);

    const float* qbase = Qt + (size_t)bh * HD * TQ + qt0;
    {
        const int rr = tid >> 4, c4 = (tid & 15) * 4;
        #pragma unroll
        for (int it = 0; it < 4; it++) {
            const int dd = rr + it*16;
            *(float4*)&Qs[dd][c4] = *(const float4*)&qbase[(size_t)dd*TQ + c4];
        }
    }

    float m_i[4], l_i[4], o[4][4];
    #pragma unroll
    for (int i = 0; i < 4; i++) {
        m_i[i] = -CUDART_INF_F; l_i[i] = 0.f;
        #pragma unroll
        for (int j = 0; j < 4; j++) o[i][j] = 0.f;
    }
    __syncthreads();

    const float* kbase = Kt + (size_t)bh * HD * KV;
    const float* vbase = V  + (size_t)bh * KV * HD;

    for (int tk = 0; tk < KV/64; tk++) {
        const int k0 = tk * 64;
        {
            const int rr = tid >> 4, c4 = (tid & 15) * 4;
            #pragma unroll
            for (int it = 0; it < 4; it++) {
                const int dd = rr + it*16;
                *(float4*)&KPs[dd][c4] = *(const float4*)&kbase[(size_t)dd*KV + k0 + c4];
                *(float4*)&Vs[dd][c4]  = *(const float4*)&vbase[(size_t)(k0+dd)*HD + c4];
            }
        }
        __syncthreads();

        float s[4][4];
        #pragma unroll
        for (int i = 0; i < 4; i++)
            #pragma unroll
            for (int j = 0; j < 4; j++) s[i][j] = 0.f;

        #pragma unroll 8
        for (int d = 0; d < 64; d++) {
            float4 qv = *(float4*)&Qs[d][ty*4];
            float4 kv = *(float4*)&KPs[d][tx*4];
            const float qa[4] = {qv.x, qv.y, qv.z, qv.w};
            const float ka[4] = {kv.x, kv.y, kv.z, kv.w};
            #pragma unroll
            for (int i = 0; i < 4; i++)
                #pragma unroll
                for (int j = 0; j < 4; j++)
                    s[i][j] = fmaf(qa[i], ka[j], s[i][j]);
        }
        // scale (+ task gating on last tile)
        #pragma unroll
        for (int j = 0; j < 4; j++) {
            const int kg = k0 + tx*4 + j;
            const float sc = 0.125f * ((kg >= TASK_OFF) ? g : 1.0f);
            #pragma unroll
            for (int i = 0; i < 4; i++) s[i][j] *= sc;
        }
        // online softmax update
        #pragma unroll
        for (int i = 0; i < 4; i++) {
            float mx = fmaxf(fmaxf(s[i][0], s[i][1]), fmaxf(s[i][2], s[i][3]));
            #pragma unroll
            for (int off = 1; off < 16; off <<= 1)
                mx = fmaxf(mx, __shfl_xor_sync(0xffffffffu, mx, off));
            const float nm = fmaxf(m_i[i], mx);
            const float corr = __expf(m_i[i] - nm);
            float rs = 0.f;
            #pragma unroll
            for (int j = 0; j < 4; j++) { s[i][j] = __expf(s[i][j] - nm); rs += s[i][j]; }
            #pragma unroll
            for (int off = 1; off < 16; off <<= 1)
                rs += __shfl_xor_sync(0xffffffffu, rs, off);
            l_i[i] = l_i[i]*corr + rs;
            m_i[i] = nm;
            #pragma unroll
            for (int j = 0; j < 4; j++) o[i][j] *= corr;
        }
        __syncthreads();
        #pragma unroll
        for (int i = 0; i < 4; i++)
            *(float4*)&KPs[ty*4+i][tx*4] = make_float4(s[i][0], s[i][1], s[i][2], s[i][3]);
        __syncthreads();
        // O += P @ V
        #pragma unroll 8
        for (int k = 0; k < 64; k++) {
            float4 vv = *(float4*)&Vs[k][tx*4];
            #pragma unroll
            for (int i = 0; i < 4; i++) {
                const float pv = KPs[ty*4+i][k];
                o[i][0] = fmaf(pv, vv.x, o[i][0]);
                o[i][1] = fmaf(pv, vv.y, o[i][1]);
                o[i][2] = fmaf(pv, vv.z, o[i][2]);
                o[i][3] = fmaf(pv, vv.w, o[i][3]);
            }
        }
        __syncthreads();
    }

    #pragma unroll
    for (int i = 0; i < 4; i++) {
        const float inv = 1.0f / l_i[i];
        const int t = qt0 + ty*4 + i;
        float4 v = make_float4(o[i][0]*inv, o[i][1]*inv, o[i][2]*inv, o[i][3]*inv);
        *(float4*)&out[(size_t)(b*TQ + t)*DIMN + h*HD + tx*4] = v;
    }
}

// ---------------- row LayerNorm ----------------
__global__ __launch_bounds__(256) void ln_kernel(
    const float* __restrict__ in, const float* __restrict__ w,
    const float* __restrict__ bz, float* __restrict__ out)
{
    const int row = blockIdx.x, tid = threadIdx.x;
    const float* xr = in + (size_t)row * DIMN;
    float4 v = ((const float4*)xr)[tid];
    float s1 = v.x + v.y + v.z + v.w;
    float s2 = v.x*v.x + v.y*v.y + v.z*v.z + v.w*v.w;
    #pragma unroll
    for (int off = 16; off; off >>= 1) {
        s1 += __shfl_xor_sync(0xffffffffu, s1, off);
        s2 += __shfl_xor_sync(0xffffffffu, s2, off);
    }
    __shared__ float sh[16];
    const int warp = tid >> 5, lane = tid & 31;
    if (lane == 0) { sh[warp] = s1; sh[8 + warp] = s2; }
    __syncthreads();
    float t1 = 0.f, t2 = 0.f;
    #pragma unroll
    for (int wi = 0; wi < 8; wi++) { t1 += sh[wi]; t2 += sh[8 + wi]; }
    const float mean = t1 * (1.0f / DIMN);
    const float var  = t2 * (1.0f / DIMN) - mean * mean;
    const float rstd = rsqrtf(var + 1e-5f);
    float4 wv = ((const float4*)w)[tid];
    float4 bv = ((const float4*)bz)[tid];
    float4 ov;
    ov.x = (v.x - mean) * rstd * wv.x + bv.x;
    ov.y = (v.y - mean) * rstd * wv.y + bv.y;
    ov.z = (v.z - mean) * rstd * wv.z + bv.z;
    ov.w = (v.w - mean) * rstd * wv.w + bv.w;
    ((float4*)(out + (size_t)row * DIMN))[tid] = ov;
}

// ---------------- launcher ----------------
extern "C" void kernel_launch(void* const* d_in, const int* in_sizes, int n_in,
                              void* d_out, int out_size)
{
    const float* x    = (const float*)d_in[0];
    const float* h_a  = (const float*)d_in[1];
    const float* h_t  = (const float*)d_in[2];
    const float* p    = (const float*)d_in[3];
    const float* Wq   = (const float*)d_in[4];  const float* bq  = (const float*)d_in[5];
    const float* Wks  = (const float*)d_in[6];  const float* bks = (const float*)d_in[7];
    const float* Wvs  = (const float*)d_in[8];  const float* bvs = (const float*)d_in[9];
    const float* Wka  = (const float*)d_in[10]; const float* bka = (const float*)d_in[11];
    const float* Wva  = (const float*)d_in[12]; const float* bva = (const float*)d_in[13];
    const float* Wkt  = (const float*)d_in[14]; const float* bkt = (const float*)d_in[15];
    const float* Wvt  = (const float*)d_in[16]; const float* bvt = (const float*)d_in[17];
    const float* Wo   = (const float*)d_in[18]; const float* bo  = (const float*)d_in[19];
    const float* Wf   = (const float*)d_in[20]; const float* bf  = (const float*)d_in[21];
    const float* gating = (const float*)d_in[22];
    const float* ln_w = (const float*)d_in[23];
    const float* ln_b = (const float*)d_in[24];
    float* outp = (float*)d_out;

    float *Qt, *Kt, *Vv, *AO, *Y, *LN;
    cudaGetSymbolAddress((void**)&Qt, g_Qt);
    cudaGetSymbolAddress((void**)&Kt, g_Kt);
    cudaGetSymbolAddress((void**)&Vv, g_V);
    cudaGetSymbolAddress((void**)&AO, g_AO);
    cudaGetSymbolAddress((void**)&Y,  g_Y);
    cudaGetSymbolAddress((void**)&LN, g_LN);

    dim3 blk(256);

    // projections (concat KV built via toff offsets; RoPE fused for q & k_self)
    gemm128<2,true ,false,false><<<dim3(8,32), blk>>>(x,   Wq,  bq,  nullptr, Qt, 4096, 2048, TQ, 0);
    gemm128<2,true ,false,false><<<dim3(8,32), blk>>>(x,   Wks, bks, nullptr, Kt, 4096, 2048, KV, 0);
    gemm128<1,false,false,false><<<dim3(8,32), blk>>>(x,   Wvs, bvs, nullptr, Vv, 4096, 2048, KV, 0);
    gemm128<2,false,false,false><<<dim3(8, 8), blk>>>(h_a, Wka, bka, nullptr, Kt, 1024,  512, KV, 2048);
    gemm128<2,false,false,false><<<dim3(8, 4), blk>>>(p,   Wka, bka, nullptr, Kt,  512,  256, KV, 2560);
    gemm128<1,false,false,false><<<dim3(8, 8), blk>>>(h_a, Wva, bva, nullptr, Vv, 1024,  512, KV, 2048);
    gemm128<1,false,false,false><<<dim3(8, 4), blk>>>(p,   Wva, bva, nullptr, Vv,  512,  256, KV, 2560);
    gemm128<2,false,false,false><<<dim3(8, 1), blk>>>(h_t, Wkt, bkt, nullptr, Kt,  128,   64, KV, 2816);
    gemm128<1,false,false,false><<<dim3(8, 1), blk>>>(h_t, Wvt, bvt, nullptr, Vv,  128,   64, KV, 2816);

    // attention over concatenated KV (scale 1/8, tanh-gated task scores)
    attn_kernel<<<dim3(TQ/64, NH, BD), blk>>>(Qt, Kt, Vv, gating, AO);

    // out proj + residual, layernorm, FFN + relu
    gemm128<0,false,true ,false><<<dim3(8,32), blk>>>(AO, Wo, bo, x,       Y,   4096, 2048, 0, 0);
    ln_kernel<<<BD*TQ, 256>>>(Y, ln_w, ln_b, LN);
    gemm128<0,false,false,true ><<<dim3(8,32), blk>>>(LN, Wf, bf, nullptr, outp,4096, 2048, 0, 0);
}

// round 3
// speedup vs baseline: 2.5006x; 2.5006x over previous
#include <cuda_runtime.h>
#include <math.h>
#include <math_constants.h>
#include <cstdint>

#define DIMN 1024
#define NH   16
#define HD   64
#define TQ   2048
#define KV   2880     // 2048 self + 768 adapter + 64 task
#define BD   2
#define TASK_OFF 2816

// ---------------- scratch (static device globals; no allocation) ----------------
__device__ float g_Qt[BD*NH*HD*TQ];   // [b][h][d][t]
__device__ float g_Kt[BD*NH*HD*KV];   // [b][h][d][k]  (concat: self|adapter|task)
__device__ float g_V [BD*NH*KV*HD];   // [b][h][k][d]
__device__ float g_AO[BD*TQ*DIMN];    // attention output (B,T,D)
__device__ float g_Y [BD*TQ*DIMN];    // post-Wo + residual
__device__ float g_LN[BD*TQ*DIMN];    // post-LN
__device__ float g_RC[HD*TQ];         // rope cos [d][t]
__device__ float g_RS[HD*TQ];         // rope sin [d][t]
__device__ float g_WT[9*DIMN*DIMN];   // transposed+tf32-rounded weights [n][k]

// ---------------- W transpose + tf32 round: WT[n][k] = rna_tf32(W[k][n]) ----------------
__global__ __launch_bounds__(256) void wtrans(const float* __restrict__ W,
                                              float* __restrict__ WT) {
    __shared__ float tile[32][33];
    const int x = threadIdx.x, y = threadIdx.y;
    const int n0 = blockIdx.x * 32, k0 = blockIdx.y * 32;
    #pragma unroll
    for (int j = 0; j < 4; j++)
        tile[y + 8*j][x] = W[(size_t)(k0 + y + 8*j) * DIMN + n0 + x];
    __syncthreads();
    #pragma unroll
    for (int j = 0; j < 4; j++) {
        float v = tile[x][y + 8*j];
        uint32_t u; asm("cvt.rna.tf32.f32 %0, %1;" : "=r"(u) : "f"(v));
        WT[(size_t)(n0 + y + 8*j) * DIMN + k0 + x] = __uint_as_float(u);
    }
}

// ======================= tf32 mma.sync GEMM, 128x128x32 tile =======================
// smem (floats): As 2*4096 | Bs 2*4096 | bias 128  -> 66048 bytes
static constexpr int SMEMF = 2*4096 + 2*4096 + 128;

// swizzled float offset for element (r, k), r in [0,128), k in [0,32)
#define SWF(r, k) ((r)*32 + ((((k) >> 2) ^ ((r) & 7)) << 2) + ((k) & 3))

// MODE 0: plain [m][n] (+RESID/+RELU); MODE 1: [b][h][k][d]; MODE 2: [b][h][d][t] (+ROPE)
template<int MODE, bool ROPE, bool RESID, bool RELU>
__global__ __launch_bounds__(256) void tgemm(
    const float* __restrict__ A, const float* __restrict__ WT,
    const float* __restrict__ bias, const float* __restrict__ resid,
    const float* __restrict__ Ctab, const float* __restrict__ Stab,
    float* __restrict__ out, int T_A, int Lout, int toff)
{
    extern __shared__ float sm[];
    float* As = sm;              // 2 buffers x 4096
    float* Bs = sm + 8192;       // 2 buffers x 4096
    float* bias_s = sm + 16384;  // 128
    const int tid = threadIdx.x;
    const int wid = tid >> 5, lid = tid & 31;
    const int gid = lid >> 2, tig = lid & 3;
    const int warp_m = wid & 3, warp_n = wid >> 2;
    const int m0 = blockIdx.y * 128, n0 = blockIdx.x * 128;

    if (tid < 32) *(float4*)&bias_s[tid*4] = *(const float4*)&bias[n0 + tid*4];

    const int lr = tid >> 3, lkq = tid & 7;       // load mapping base (i adds 32 rows)
    const float* Ap  = A  + (size_t)(m0 + lr) * DIMN + lkq * 4;
    const float* Wp  = WT + (size_t)(n0 + lr) * DIMN + lkq * 4;

    float accu[2][8][4];
    #pragma unroll
    for (int mt = 0; mt < 2; mt++)
        #pragma unroll
        for (int nt = 0; nt < 8; nt++)
            #pragma unroll
            for (int c = 0; c < 4; c++) accu[mt][nt][c] = 0.f;

    // ---- stage 0 ----
    #pragma unroll
    for (int i = 0; i < 4; i++) {
        const int r = lr + 32*i;
        float4 va = *(const float4*)(Ap + (size_t)32*i*DIMN);
        uint4 ua;
        asm("cvt.rna.tf32.f32 %0, %1;" : "=r"(ua.x) : "f"(va.x));
        asm("cvt.rna.tf32.f32 %0, %1;" : "=r"(ua.y) : "f"(va.y));
        asm("cvt.rna.tf32.f32 %0, %1;" : "=r"(ua.z) : "f"(va.z));
        asm("cvt.rna.tf32.f32 %0, %1;" : "=r"(ua.w) : "f"(va.w));
        *(uint4*)&As[SWF(r, lkq*4)] = ua;
        *(float4*)&Bs[SWF(r, lkq*4)] = *(const float4*)(Wp + (size_t)32*i*DIMN);
    }
    __syncthreads();

    for (int kc = 0; kc < 32; kc++) {
        const int cur = kc & 1;
        float4 pa[4], pb[4];
        if (kc < 31) {
            #pragma unroll
            for (int i = 0; i < 4; i++) {
                pa[i] = *(const float4*)(Ap + (size_t)32*i*DIMN + (kc+1)*32);
                pb[i] = *(const float4*)(Wp + (size_t)32*i*DIMN + (kc+1)*32);
            }
        }
        const float* as_ = As + cur*4096;
        const float* bs_ = Bs + cur*4096;
        #pragma unroll
        for (int ks = 0; ks < 4; ks++) {
            const int g0 = ((2*ks) ^ gid) << 2, g1 = ((2*ks+1) ^ gid) << 2;
            uint32_t af[2][4], bf[8][2];
            #pragma unroll
            for (int mt = 0; mt < 2; mt++) {
                const int mr = warp_m*32 + mt*16 + gid;
                af[mt][0] = __float_as_uint(as_[mr*32       + g0 + tig]);
                af[mt][1] = __float_as_uint(as_[(mr+8)*32   + g0 + tig]);
                af[mt][2] = __float_as_uint(as_[mr*32       + g1 + tig]);
                af[mt][3] = __float_as_uint(as_[(mr+8)*32   + g1 + tig]);
            }
            #pragma unroll
            for (int nt = 0; nt < 8; nt++) {
                const int nr = warp_n*64 + nt*8 + gid;
                bf[nt][0] = __float_as_uint(bs_[nr*32 + g0 + tig]);
                bf[nt][1] = __float_as_uint(bs_[nr*32 + g1 + tig]);
            }
            #pragma unroll
            for (int mt = 0; mt < 2; mt++)
                #pragma unroll
                for (int nt = 0; nt < 8; nt++)
                    asm volatile(
                        "mma.sync.aligned.m16n8k8.row.col.f32.tf32.tf32.f32 "
                        "{%0,%1,%2,%3}, {%4,%5,%6,%7}, {%8,%9}, {%0,%1,%2,%3};"
                        : "+f"(accu[mt][nt][0]), "+f"(accu[mt][nt][1]),
                          "+f"(accu[mt][nt][2]), "+f"(accu[mt][nt][3])
                        : "r"(af[mt][0]), "r"(af[mt][1]), "r"(af[mt][2]), "r"(af[mt][3]),
                          "r"(bf[nt][0]), "r"(bf[nt][1]));
        }
        if (kc < 31) {
            const int nxt = cur ^ 1;
            float* an = As + nxt*4096;
            float* bn = Bs + nxt*4096;
            #pragma unroll
            for (int i = 0; i < 4; i++) {
                const int r = lr + 32*i;
                uint4 ua;
                asm("cvt.rna.tf32.f32 %0, %1;" : "=r"(ua.x) : "f"(pa[i].x));
                asm("cvt.rna.tf32.f32 %0, %1;" : "=r"(ua.y) : "f"(pa[i].y));
                asm("cvt.rna.tf32.f32 %0, %1;" : "=r"(ua.z) : "f"(pa[i].z));
                asm("cvt.rna.tf32.f32 %0, %1;" : "=r"(ua.w) : "f"(pa[i].w));
                *(uint4*)&an[SWF(r, lkq*4)] = ua;
                *(float4*)&bn[SWF(r, lkq*4)] = pb[i];
            }
        }
        __syncthreads();
    }

    // ---- epilogue ----
    #pragma unroll
    for (int mt = 0; mt < 2; mt++) {
        #pragma unroll
        for (int half = 0; half < 2; half++) {
            const int m = m0 + warp_m*32 + mt*16 + gid + half*8;
            const int t = m % T_A, bb = m / T_A;
            #pragma unroll
            for (int nt = 0; nt < 8; nt++) {
                const int nc = warp_n*64 + nt*8 + tig*2;
                const int n = n0 + nc;
                float c0 = accu[mt][nt][half*2+0] + bias_s[nc];
                float c1 = accu[mt][nt][half*2+1] + bias_s[nc+1];
                if (MODE == 0) {
                    float2 o = make_float2(c0, c1);
                    if (RESID) {
                        float2 rx = *(const float2*)&resid[(size_t)m*DIMN + n];
                        o.x += rx.x; o.y += rx.y;
                    }
                    if (RELU) { o.x = fmaxf(o.x, 0.f); o.y = fmaxf(o.y, 0.f); }
                    *(float2*)&out[(size_t)m*DIMN + n] = o;
                } else if (MODE == 1) {
                    const int h = n >> 6, d = n & 63;
                    *(float2*)&out[((size_t)(bb*NH + h)*Lout + toff + t)*HD + d] =
                        make_float2(c0, c1);
                } else {
                    const int h = n >> 6, d = n & 63;
                    if (ROPE) {
                        const float ce = Ctab[d*TQ + t],     se = Stab[d*TQ + t];
                        const float co = Ctab[(d+1)*TQ + t], so = Stab[(d+1)*TQ + t];
                        const float e = c0*ce - c1*se;
                        const float o = c1*co + c0*so;
                        c0 = e; c1 = o;
                    }
                    const size_t rowb = (size_t)(bb*NH + h)*HD;
                    out[(rowb + d)     * Lout + toff + t] = c0;
                    out[(rowb + d + 1) * Lout + toff + t] = c1;
                }
            }
        }
    }
}

// ---------------- rope tables [d][t] ----------------
__global__ void rope_tables(float* __restrict__ C, float* __restrict__ S) {
    const int t = blockIdx.x * 256 + threadIdx.x;
    const int d = blockIdx.y;
    const float C1 = 0.28782313662425572f;  // ln(10000)/32
    const float inv = expf(-(float)(d & 31) * C1);
    float se, ce;
    sincosf((float)t * inv, &se, &ce);
    C[d * TQ + t] = ce;
    S[d * TQ + t] = se;
}

// ---------------- flash-style attention over concatenated KV (fp32 SIMT) ----------------
__global__ __launch_bounds__(256) void attn_kernel(
    const float* __restrict__ Qt, const float* __restrict__ Kt,
    const float* __restrict__ V, const float* __restrict__ gate,
    float* __restrict__ out)
{
    __shared__ float Qs[64][64];   // [d][r]
    __shared__ float KPs[64][64];  // K as [d][c], reused as P [r][c]
    __shared__ float Vs[64][64];   // [c][d]
    const int tid = threadIdx.x, tx = tid & 15, ty = tid >> 4;
    const int qt0 = blockIdx.x * 64;
    const int h = blockIdx.y, b = blockIdx.z;
    const int bh = b * NH + h;
    const float g = tanhf(gate[0]);

    const float* qbase = Qt + (size_t)bh * HD * TQ + qt0;
    {
        const int rr = tid >> 4, c4 = (tid & 15) * 4;
        #pragma unroll
        for (int it = 0; it < 4; it++) {
            const int dd = rr + it*16;
            *(float4*)&Qs[dd][c4] = *(const float4*)&qbase[(size_t)dd*TQ + c4];
        }
    }

    float m_i[4], l_i[4], o[4][4];
    #pragma unroll
    for (int i = 0; i < 4; i++) {
        m_i[i] = -CUDART_INF_F; l_i[i] = 0.f;
        #pragma unroll
        for (int j = 0; j < 4; j++) o[i][j] = 0.f;
    }
    __syncthreads();

    const float* kbase = Kt + (size_t)bh * HD * KV;
    const float* vbase = V  + (size_t)bh * KV * HD;

    for (int tk = 0; tk < KV/64; tk++) {
        const int k0 = tk * 64;
        {
            const int rr = tid >> 4, c4 = (tid & 15) * 4;
            #pragma unroll
            for (int it = 0; it < 4; it++) {
                const int dd = rr + it*16;
                *(float4*)&KPs[dd][c4] = *(const float4*)&kbase[(size_t)dd*KV + k0 + c4];
                *(float4*)&Vs[dd][c4]  = *(const float4*)&vbase[(size_t)(k0+dd)*HD + c4];
            }
        }
        __syncthreads();

        float s[4][4];
        #pragma unroll
        for (int i = 0; i < 4; i++)
            #pragma unroll
            for (int j = 0; j < 4; j++) s[i][j] = 0.f;

        #pragma unroll 8
        for (int d = 0; d < 64; d++) {
            float4 qv = *(float4*)&Qs[d][ty*4];
            float4 kv = *(float4*)&KPs[d][tx*4];
            const float qa[4] = {qv.x, qv.y, qv.z, qv.w};
            const float ka[4] = {kv.x, kv.y, kv.z, kv.w};
            #pragma unroll
            for (int i = 0; i < 4; i++)
                #pragma unroll
                for (int j = 0; j < 4; j++)
                    s[i][j] = fmaf(qa[i], ka[j], s[i][j]);
        }
        #pragma unroll
        for (int j = 0; j < 4; j++) {
            const int kg = k0 + tx*4 + j;
            const float sc = 0.125f * ((kg >= TASK_OFF) ? g : 1.0f);
            #pragma unroll
            for (int i = 0; i < 4; i++) s[i][j] *= sc;
        }
        #pragma unroll
        for (int i = 0; i < 4; i++) {
            float mx = fmaxf(fmaxf(s[i][0], s[i][1]), fmaxf(s[i][2], s[i][3]));
            #pragma unroll
            for (int off = 1; off < 16; off <<= 1)
                mx = fmaxf(mx, __shfl_xor_sync(0xffffffffu, mx, off));
            const float nm = fmaxf(m_i[i], mx);
            const float corr = __expf(m_i[i] - nm);
            float rs = 0.f;
            #pragma unroll
            for (int j = 0; j < 4; j++) { s[i][j] = __expf(s[i][j] - nm); rs += s[i][j]; }
            #pragma unroll
            for (int off = 1; off < 16; off <<= 1)
                rs += __shfl_xor_sync(0xffffffffu, rs, off);
            l_i[i] = l_i[i]*corr + rs;
            m_i[i] = nm;
            #pragma unroll
            for (int j = 0; j < 4; j++) o[i][j] *= corr;
        }
        __syncthreads();
        #pragma unroll
        for (int i = 0; i < 4; i++)
            *(float4*)&KPs[ty*4+i][tx*4] = make_float4(s[i][0], s[i][1], s[i][2], s[i][3]);
        __syncthreads();
        #pragma unroll 8
        for (int k = 0; k < 64; k++) {
            float4 vv = *(float4*)&Vs[k][tx*4];
            #pragma unroll
            for (int i = 0; i < 4; i++) {
                const float pv = KPs[ty*4+i][k];
                o[i][0] = fmaf(pv, vv.x, o[i][0]);
                o[i][1] = fmaf(pv, vv.y, o[i][1]);
                o[i][2] = fmaf(pv, vv.z, o[i][2]);
                o[i][3] = fmaf(pv, vv.w, o[i][3]);
            }
        }
        __syncthreads();
    }

    #pragma unroll
    for (int i = 0; i < 4; i++) {
        const float inv = 1.0f / l_i[i];
        const int t = qt0 + ty*4 + i;
        float4 v = make_float4(o[i][0]*inv, o[i][1]*inv, o[i][2]*inv, o[i][3]*inv);
        *(float4*)&out[(size_t)(b*TQ + t)*DIMN + h*HD + tx*4] = v;
    }
}

// ---------------- row LayerNorm ----------------
__global__ __launch_bounds__(256) void ln_kernel(
    const float* __restrict__ in, const float* __restrict__ w,
    const float* __restrict__ bz, float* __restrict__ out)
{
    const int row = blockIdx.x, tid = threadIdx.x;
    const float* xr = in + (size_t)row * DIMN;
    float4 v = ((const float4*)xr)[tid];
    float s1 = v.x + v.y + v.z + v.w;
    float s2 = v.x*v.x + v.y*v.y + v.z*v.z + v.w*v.w;
    #pragma unroll
    for (int off = 16; off; off >>= 1) {
        s1 += __shfl_xor_sync(0xffffffffu, s1, off);
        s2 += __shfl_xor_sync(0xffffffffu, s2, off);
    }
    __shared__ float sh[16];
    const int warp = tid >> 5, lane = tid & 31;
    if (lane == 0) { sh[warp] = s1; sh[8 + warp] = s2; }
    __syncthreads();
    float t1 = 0.f, t2 = 0.f;
    #pragma unroll
    for (int wi = 0; wi < 8; wi++) { t1 += sh[wi]; t2 += sh[8 + wi]; }
    const float mean = t1 * (1.0f / DIMN);
    const float var  = t2 * (1.0f / DIMN) - mean * mean;
    const float rstd = rsqrtf(var + 1e-5f);
    float4 wv = ((const float4*)w)[tid];
    float4 bv = ((const float4*)bz)[tid];
    float4 ov;
    ov.x = (v.x - mean) * rstd * wv.x + bv.x;
    ov.y = (v.y - mean) * rstd * wv.y + bv.y;
    ov.z = (v.z - mean) * rstd * wv.z + bv.z;
    ov.w = (v.w - mean) * rstd * wv.w + bv.w;
    ((float4*)(out + (size_t)row * DIMN))[tid] = ov;
}

// ---------------- launcher ----------------
extern "C" void kernel_launch(void* const* d_in, const int* in_sizes, int n_in,
                              void* d_out, int out_size)
{
    const float* x    = (const float*)d_in[0];
    const float* h_a  = (const float*)d_in[1];
    const float* h_t  = (const float*)d_in[2];
    const float* p    = (const float*)d_in[3];
    const float* Wq   = (const float*)d_in[4];  const float* bq  = (const float*)d_in[5];
    const float* Wks  = (const float*)d_in[6];  const float* bks = (const float*)d_in[7];
    const float* Wvs  = (const float*)d_in[8];  const float* bvs = (const float*)d_in[9];
    const float* Wka  = (const float*)d_in[10]; const float* bka = (const float*)d_in[11];
    const float* Wva  = (const float*)d_in[12]; const float* bva = (const float*)d_in[13];
    const float* Wkt  = (const float*)d_in[14]; const float* bkt = (const float*)d_in[15];
    const float* Wvt  = (const float*)d_in[16]; const float* bvt = (const float*)d_in[17];
    const float* Wo   = (const float*)d_in[18]; const float* bo  = (const float*)d_in[19];
    const float* Wf   = (const float*)d_in[20]; const float* bf  = (const float*)d_in[21];
    const float* gating = (const float*)d_in[22];
    const float* ln_w = (const float*)d_in[23];
    const float* ln_b = (const float*)d_in[24];
    float* outp = (float*)d_out;

    float *Qt, *Kt, *Vv, *AO, *Y, *LN, *RC, *RS, *WTb;
    cudaGetSymbolAddress((void**)&Qt, g_Qt);
    cudaGetSymbolAddress((void**)&Kt, g_Kt);
    cudaGetSymbolAddress((void**)&Vv, g_V);
    cudaGetSymbolAddress((void**)&AO, g_AO);
    cudaGetSymbolAddress((void**)&Y,  g_Y);
    cudaGetSymbolAddress((void**)&LN, g_LN);
    cudaGetSymbolAddress((void**)&RC, g_RC);
    cudaGetSymbolAddress((void**)&RS, g_RS);
    cudaGetSymbolAddress((void**)&WTb, g_WT);

    const size_t WSZ = (size_t)DIMN * DIMN;
    float* WTq  = WTb + 0*WSZ;  float* WTks = WTb + 1*WSZ;  float* WTvs = WTb + 2*WSZ;
    float* WTka = WTb + 3*WSZ;  float* WTva = WTb + 4*WSZ;  float* WTkt = WTb + 5*WSZ;
    float* WTvt = WTb + 6*WSZ;  float* WTo  = WTb + 7*WSZ;  float* WTf  = WTb + 8*WSZ;

    const int smemb = SMEMF * 4;
    cudaFuncSetAttribute(tgemm<0,false,true ,false>, cudaFuncAttributeMaxDynamicSharedMemorySize, smemb);
    cudaFuncSetAttribute(tgemm<0,false,false,true >, cudaFuncAttributeMaxDynamicSharedMemorySize, smemb);
    cudaFuncSetAttribute(tgemm<1,false,false,false>, cudaFuncAttributeMaxDynamicSharedMemorySize, smemb);
    cudaFuncSetAttribute(tgemm<2,true ,false,false>, cudaFuncAttributeMaxDynamicSharedMemorySize, smemb);
    cudaFuncSetAttribute(tgemm<2,false,false,false>, cudaFuncAttributeMaxDynamicSharedMemorySize, smemb);

    dim3 blk(256);
    dim3 tgrid(32, 32), tblk(32, 8);

    rope_tables<<<dim3(TQ/256, HD), 256>>>(RC, RS);
    wtrans<<<tgrid, tblk>>>(Wq,  WTq );
    wtrans<<<tgrid, tblk>>>(Wks, WTks);
    wtrans<<<tgrid, tblk>>>(Wvs, WTvs);
    wtrans<<<tgrid, tblk>>>(Wka, WTka);
    wtrans<<<tgrid, tblk>>>(Wva, WTva);
    wtrans<<<tgrid, tblk>>>(Wkt, WTkt);
    wtrans<<<tgrid, tblk>>>(Wvt, WTvt);
    wtrans<<<tgrid, tblk>>>(Wo,  WTo );
    wtrans<<<tgrid, tblk>>>(Wf,  WTf );

    // projections (concat KV via toff; RoPE fused for q & k_self)
    tgemm<2,true ,false,false><<<dim3(8,32), blk, smemb>>>(x,   WTq,  bq,  nullptr, RC, RS, Qt, 2048, TQ, 0);
    tgemm<2,true ,false,false><<<dim3(8,32), blk, smemb>>>(x,   WTks, bks, nullptr, RC, RS, Kt, 2048, KV, 0);
    tgemm<1,false,false,false><<<dim3(8,32), blk, smemb>>>(x,   WTvs, bvs, nullptr, nullptr, nullptr, Vv, 2048, KV, 0);
    tgemm<2,false,false,false><<<dim3(8, 8), blk, smemb>>>(h_a, WTka, bka, nullptr, nullptr, nullptr, Kt,  512, KV, 2048);
    tgemm<2,false,false,false><<<dim3(8, 4), blk, smemb>>>(p,   WTka, bka, nullptr, nullptr, nullptr, Kt,  256, KV, 2560);
    tgemm<1,false,false,false><<<dim3(8, 8), blk, smemb>>>(h_a, WTva, bva, nullptr, nullptr, nullptr, Vv,  512, KV, 2048);
    tgemm<1,false,false,false><<<dim3(8, 4), blk, smemb>>>(p,   WTva, bva, nullptr, nullptr, nullptr, Vv,  256, KV, 2560);
    tgemm<2,false,false,false><<<dim3(8, 1), blk, smemb>>>(h_t, WTkt, bkt, nullptr, nullptr, nullptr, Kt,   64, KV, 2816);
    tgemm<1,false,false,false><<<dim3(8, 1), blk, smemb>>>(h_t, WTvt, bvt, nullptr, nullptr, nullptr, Vv,   64, KV, 2816);

    // attention over concatenated KV (scale 1/8, tanh-gated task scores)
    attn_kernel<<<dim3(TQ/64, NH, BD), blk>>>(Qt, Kt, Vv, gating, AO);

    // out proj + residual, layernorm, FFN + relu
    tgemm<0,false,true ,false><<<dim3(8,32), blk, smemb>>>(AO, WTo, bo, x,       nullptr, nullptr, Y,    2048, 0, 0);
    ln_kernel<<<BD*TQ, 256>>>(Y, ln_w, ln_b, LN);
    tgemm<0,false,false,true ><<<dim3(8,32), blk, smemb>>>(LN, WTf, bf, nullptr, nullptr, nullptr, outp, 2048, 0, 0);
}

// round 4
// speedup vs baseline: 4.3059x; 1.7219x over previous
#include <cuda_runtime.h>
#include <math.h>
#include <math_constants.h>
#include <cstdint>

#define DIMN 1024
#define NH   16
#define HD   64
#define TQ   2048
#define KV   2880     // 2048 self + 768 adapter + 64 task
#define BD   2
#define TASK_OFF 2816

// ---------------- scratch (static device globals; no allocation) ----------------
__device__ float g_Qt[BD*NH*HD*TQ];   // [b][h][d][t]
__device__ float g_Kt[BD*NH*HD*KV];   // [b][h][d][k]  (concat: self|adapter|task)
__device__ float g_V [BD*NH*KV*HD];   // [b][h][k][d]
__device__ float g_AO[BD*TQ*DIMN];    // attention output (B,T,D)
__device__ float g_Y [BD*TQ*DIMN];    // post-Wo + residual
__device__ float g_LN[BD*TQ*DIMN];    // post-LN
__device__ float g_RC[HD*TQ];         // rope cos [d][t]
__device__ float g_RS[HD*TQ];         // rope sin [d][t]
__device__ float g_WT[9*DIMN*DIMN];   // transposed+tf32-rounded weights [n][k]

__device__ __forceinline__ float tf32r(float v) {
    uint32_t u; asm("cvt.rna.tf32.f32 %0, %1;" : "=r"(u) : "f"(v));
    return __uint_as_float(u);
}

// ---------------- W transpose + tf32 round: WT[n][k] = rna_tf32(W[k][n]) ----------------
__global__ __launch_bounds__(256) void wtrans(const float* __restrict__ W,
                                              float* __restrict__ WT) {
    __shared__ float tile[32][33];
    const int x = threadIdx.x, y = threadIdx.y;
    const int n0 = blockIdx.x * 32, k0 = blockIdx.y * 32;
    #pragma unroll
    for (int j = 0; j < 4; j++)
        tile[y + 8*j][x] = W[(size_t)(k0 + y + 8*j) * DIMN + n0 + x];
    __syncthreads();
    #pragma unroll
    for (int j = 0; j < 4; j++)
        WT[(size_t)(n0 + y + 8*j) * DIMN + k0 + x] = tf32r(tile[x][y + 8*j]);
}

// ======================= tf32 mma.sync GEMM, 128x128x32 tile =======================
static constexpr int SMEMF = 2*4096 + 2*4096 + 128;
#define SWF(r, k) ((r)*32 + ((((k) >> 2) ^ ((r) & 7)) << 2) + ((k) & 3))

// MODE 0: plain [m][n] (+RESID/+RELU); MODE 1: [b][h][k][d]; MODE 2: [b][h][d][t] (+ROPE)
// TF32O: round outputs to tf32 pattern (for attention operands)
template<int MODE, bool ROPE, bool RESID, bool RELU, bool TF32O>
__global__ __launch_bounds__(256) void tgemm(
    const float* __restrict__ A, const float* __restrict__ WT,
    const float* __restrict__ bias, const float* __restrict__ resid,
    const float* __restrict__ Ctab, const float* __restrict__ Stab,
    float* __restrict__ out, int T_A, int Lout, int toff)
{
    extern __shared__ float sm[];
    float* As = sm;              // 2 buffers x 4096
    float* Bs = sm + 8192;       // 2 buffers x 4096
    float* bias_s = sm + 16384;  // 128
    const int tid = threadIdx.x;
    const int wid = tid >> 5, lid = tid & 31;
    const int gid = lid >> 2, tig = lid & 3;
    const int warp_m = wid & 3, warp_n = wid >> 2;
    const int m0 = blockIdx.y * 128, n0 = blockIdx.x * 128;

    if (tid < 32) *(float4*)&bias_s[tid*4] = *(const float4*)&bias[n0 + tid*4];

    const int lr = tid >> 3, lkq = tid & 7;
    const float* Ap  = A  + (size_t)(m0 + lr) * DIMN + lkq * 4;
    const float* Wp  = WT + (size_t)(n0 + lr) * DIMN + lkq * 4;

    float accu[2][8][4];
    #pragma unroll
    for (int mt = 0; mt < 2; mt++)
        #pragma unroll
        for (int nt = 0; nt < 8; nt++)
            #pragma unroll
            for (int c = 0; c < 4; c++) accu[mt][nt][c] = 0.f;

    #pragma unroll
    for (int i = 0; i < 4; i++) {
        const int r = lr + 32*i;
        float4 va = *(const float4*)(Ap + (size_t)32*i*DIMN);
        va.x = tf32r(va.x); va.y = tf32r(va.y); va.z = tf32r(va.z); va.w = tf32r(va.w);
        *(float4*)&As[SWF(r, lkq*4)] = va;
        *(float4*)&Bs[SWF(r, lkq*4)] = *(const float4*)(Wp + (size_t)32*i*DIMN);
    }
    __syncthreads();

    for (int kc = 0; kc < 32; kc++) {
        const int cur = kc & 1;
        float4 pa[4], pb[4];
        if (kc < 31) {
            #pragma unroll
            for (int i = 0; i < 4; i++) {
                pa[i] = *(const float4*)(Ap + (size_t)32*i*DIMN + (kc+1)*32);
                pb[i] = *(const float4*)(Wp + (size_t)32*i*DIMN + (kc+1)*32);
            }
        }
        const float* as_ = As + cur*4096;
        const float* bs_ = Bs + cur*4096;
        #pragma unroll
        for (int ks = 0; ks < 4; ks++) {
            const int g0 = ((2*ks) ^ gid) << 2, g1 = ((2*ks+1) ^ gid) << 2;
            uint32_t af[2][4], bf[8][2];
            #pragma unroll
            for (int mt = 0; mt < 2; mt++) {
                const int mr = warp_m*32 + mt*16 + gid;
                af[mt][0] = __float_as_uint(as_[mr*32       + g0 + tig]);
                af[mt][1] = __float_as_uint(as_[(mr+8)*32   + g0 + tig]);
                af[mt][2] = __float_as_uint(as_[mr*32       + g1 + tig]);
                af[mt][3] = __float_as_uint(as_[(mr+8)*32   + g1 + tig]);
            }
            #pragma unroll
            for (int nt = 0; nt < 8; nt++) {
                const int nr = warp_n*64 + nt*8 + gid;
                bf[nt][0] = __float_as_uint(bs_[nr*32 + g0 + tig]);
                bf[nt][1] = __float_as_uint(bs_[nr*32 + g1 + tig]);
            }
            #pragma unroll
            for (int mt = 0; mt < 2; mt++)
                #pragma unroll
                for (int nt = 0; nt < 8; nt++)
                    asm volatile(
                        "mma.sync.aligned.m16n8k8.row.col.f32.tf32.tf32.f32 "
                        "{%0,%1,%2,%3}, {%4,%5,%6,%7}, {%8,%9}, {%0,%1,%2,%3};"
                        : "+f"(accu[mt][nt][0]), "+f"(accu[mt][nt][1]),
                          "+f"(accu[mt][nt][2]), "+f"(accu[mt][nt][3])
                        : "r"(af[mt][0]), "r"(af[mt][1]), "r"(af[mt][2]), "r"(af[mt][3]),
                          "r"(bf[nt][0]), "r"(bf[nt][1]));
        }
        if (kc < 31) {
            const int nxt = cur ^ 1;
            float* an = As + nxt*4096;
            float* bn = Bs + nxt*4096;
            #pragma unroll
            for (int i = 0; i < 4; i++) {
                const int r = lr + 32*i;
                pa[i].x = tf32r(pa[i].x); pa[i].y = tf32r(pa[i].y);
                pa[i].z = tf32r(pa[i].z); pa[i].w = tf32r(pa[i].w);
                *(float4*)&an[SWF(r, lkq*4)] = pa[i];
                *(float4*)&bn[SWF(r, lkq*4)] = pb[i];
            }
        }
        __syncthreads();
    }

    // ---- epilogue ----
    #pragma unroll
    for (int mt = 0; mt < 2; mt++) {
        #pragma unroll
        for (int half = 0; half < 2; half++) {
            const int m = m0 + warp_m*32 + mt*16 + gid + half*8;
            const int t = m % T_A, bb = m / T_A;
            #pragma unroll
            for (int nt = 0; nt < 8; nt++) {
                const int nc = warp_n*64 + nt*8 + tig*2;
                const int n = n0 + nc;
                float c0 = accu[mt][nt][half*2+0] + bias_s[nc];
                float c1 = accu[mt][nt][half*2+1] + bias_s[nc+1];
                if (MODE == 0) {
                    float2 o = make_float2(c0, c1);
                    if (RESID) {
                        float2 rx = *(const float2*)&resid[(size_t)m*DIMN + n];
                        o.x += rx.x; o.y += rx.y;
                    }
                    if (RELU) { o.x = fmaxf(o.x, 0.f); o.y = fmaxf(o.y, 0.f); }
                    *(float2*)&out[(size_t)m*DIMN + n] = o;
                } else {
                    const int hh = n >> 6, d = n & 63;
                    if (ROPE) {
                        const float ce = Ctab[d*TQ + t],     se = Stab[d*TQ + t];
                        const float co = Ctab[(d+1)*TQ + t], so = Stab[(d+1)*TQ + t];
                        const float e = c0*ce - c1*se;
                        const float o = c1*co + c0*so;
                        c0 = e; c1 = o;
                    }
                    if (TF32O) { c0 = tf32r(c0); c1 = tf32r(c1); }
                    if (MODE == 1) {
                        *(float2*)&out[((size_t)(bb*NH + hh)*Lout + toff + t)*HD + d] =
                            make_float2(c0, c1);
                    } else {
                        const size_t rowb = (size_t)(bb*NH + hh)*HD;
                        out[(rowb + d)     * Lout + toff + t] = c0;
                        out[(rowb + d + 1) * Lout + toff + t] = c1;
                    }
                }
            }
        }
    }
}

// ---------------- rope tables [d][t] ----------------
__global__ void rope_tables(float* __restrict__ C, float* __restrict__ S) {
    const int t = blockIdx.x * 256 + threadIdx.x;
    const int d = blockIdx.y;
    const float C1 = 0.28782313662425572f;  // ln(10000)/32
    const float inv = expf(-(float)(d & 31) * C1);
    float se, ce;
    sincosf((float)t * inv, &se, &ce);
    C[d * TQ + t] = ce;
    S[d * TQ + t] = se;
}

// ======================= mma.sync tf32 flash attention =======================
// 64-q tile, 128 threads (4 warps x 16 q rows), full KV loop, online softmax.
// Smem (stride 72 pad, all fragment LDS conflict-free):
//   Qs[d][t]  <- g_Qt [b][h][d][t]
//   Ks[d][k]  <- g_Kt [b][h][d][k]    (aliased by Ps[k][q] after S-mma)
//   Vs[k][d]  <- g_V  [b][h][k][d]
#define AST 72
static constexpr int ATT_SMEM = 3 * 64 * AST * 4;  // 55296 bytes

__global__ __launch_bounds__(128) void attn_mma(
    const float* __restrict__ Qt, const float* __restrict__ Kt,
    const float* __restrict__ Vv, const float* __restrict__ gate,
    float* __restrict__ out)
{
    extern __shared__ float sm[];
    float* Qs = sm;              // 64*72
    float* KP = sm + 64*AST;     // Ks[d][k] then Ps[k][q]
    float* Vs = sm + 2*64*AST;   // Vs[k][d]
    const int tid = threadIdx.x;
    const int wid = tid >> 5, lane = tid & 31;
    const int gid = lane >> 2, tig = lane & 3;
    const int tw = wid * 16;
    const int qt0 = blockIdx.x * 64;
    const int h = blockIdx.y, b = blockIdx.z, bh = b*NH + h;
    const float g = tanhf(gate[0]);

    // load Q tile (already tf32-rounded at projection)
    const float* qbase = Qt + (size_t)bh*HD*TQ + qt0;
    #pragma unroll
    for (int it = 0; it < 8; it++) {
        const int idx = tid + 128*it;
        const int d = idx >> 4, t0 = (idx & 15) * 4;
        *(float4*)&Qs[d*AST + t0] = *(const float4*)&qbase[(size_t)d*TQ + t0];
    }

    float m0r = -CUDART_INF_F, m1r = -CUDART_INF_F, l0r = 0.f, l1r = 0.f;
    float oa[8][4];
    #pragma unroll
    for (int nt = 0; nt < 8; nt++)
        #pragma unroll
        for (int c = 0; c < 4; c++) oa[nt][c] = 0.f;
    __syncthreads();

    const float* kbase = Kt + (size_t)bh*HD*KV;
    const float* vbase = Vv + (size_t)bh*KV*HD;

    for (int tk = 0; tk < KV/64; tk++) {
        const int k0 = tk * 64;
        #pragma unroll
        for (int it = 0; it < 8; it++) {
            const int idx = tid + 128*it;
            const int r = idx >> 4, c0 = (idx & 15) * 4;
            *(float4*)&KP[r*AST + c0] = *(const float4*)&kbase[(size_t)r*KV + k0 + c0];
            *(float4*)&Vs[r*AST + c0] = *(const float4*)&vbase[(size_t)(k0 + r)*HD + c0];
        }
        __syncthreads();

        // ---- S = Q^T K (M=q, N=k, K=d) ----
        float sacc[8][4];
        #pragma unroll
        for (int nt = 0; nt < 8; nt++)
            #pragma unroll
            for (int c = 0; c < 4; c++) sacc[nt][c] = 0.f;
        #pragma unroll
        for (int ks = 0; ks < 8; ks++) {
            uint32_t a0 = __float_as_uint(Qs[(ks*8+tig)*AST   + tw + gid]);
            uint32_t a1 = __float_as_uint(Qs[(ks*8+tig)*AST   + tw + gid + 8]);
            uint32_t a2 = __float_as_uint(Qs[(ks*8+4+tig)*AST + tw + gid]);
            uint32_t a3 = __float_as_uint(Qs[(ks*8+4+tig)*AST + tw + gid + 8]);
            #pragma unroll
            for (int nt = 0; nt < 8; nt++) {
                uint32_t b0 = __float_as_uint(KP[(ks*8+tig)*AST   + nt*8 + gid]);
                uint32_t b1 = __float_as_uint(KP[(ks*8+4+tig)*AST + nt*8 + gid]);
                asm volatile(
                    "mma.sync.aligned.m16n8k8.row.col.f32.tf32.tf32.f32 "
                    "{%0,%1,%2,%3}, {%4,%5,%6,%7}, {%8,%9}, {%0,%1,%2,%3};"
                    : "+f"(sacc[nt][0]), "+f"(sacc[nt][1]),
                      "+f"(sacc[nt][2]), "+f"(sacc[nt][3])
                    : "r"(a0), "r"(a1), "r"(a2), "r"(a3), "r"(b0), "r"(b1));
            }
        }

        // ---- online softmax (rows tw+gid, tw+gid+8; quad shfl reductions) ----
        const float sc = (k0 == TASK_OFF) ? 0.125f * g : 0.125f;
        float mx0 = -CUDART_INF_F, mx1 = -CUDART_INF_F;
        #pragma unroll
        for (int nt = 0; nt < 8; nt++) {
            sacc[nt][0] *= sc; sacc[nt][1] *= sc; sacc[nt][2] *= sc; sacc[nt][3] *= sc;
            mx0 = fmaxf(mx0, fmaxf(sacc[nt][0], sacc[nt][1]));
            mx1 = fmaxf(mx1, fmaxf(sacc[nt][2], sacc[nt][3]));
        }
        #pragma unroll
        for (int off = 1; off < 4; off <<= 1) {
            mx0 = fmaxf(mx0, __shfl_xor_sync(0xffffffffu, mx0, off));
            mx1 = fmaxf(mx1, __shfl_xor_sync(0xffffffffu, mx1, off));
        }
        const float nm0 = fmaxf(m0r, mx0), nm1 = fmaxf(m1r, mx1);
        const float corr0 = __expf(m0r - nm0), corr1 = __expf(m1r - nm1);
        m0r = nm0; m1r = nm1;
        float rs0 = 0.f, rs1 = 0.f;
        #pragma unroll
        for (int nt = 0; nt < 8; nt++) {
            sacc[nt][0] = __expf(sacc[nt][0] - nm0);
            sacc[nt][1] = __expf(sacc[nt][1] - nm0);
            sacc[nt][2] = __expf(sacc[nt][2] - nm1);
            sacc[nt][3] = __expf(sacc[nt][3] - nm1);
            rs0 += sacc[nt][0] + sacc[nt][1];
            rs1 += sacc[nt][2] + sacc[nt][3];
        }
        #pragma unroll
        for (int off = 1; off < 4; off <<= 1) {
            rs0 += __shfl_xor_sync(0xffffffffu, rs0, off);
            rs1 += __shfl_xor_sync(0xffffffffu, rs1, off);
        }
        l0r = l0r * corr0 + rs0;
        l1r = l1r * corr1 + rs1;
        #pragma unroll
        for (int nt = 0; nt < 8; nt++) {
            oa[nt][0] *= corr0; oa[nt][1] *= corr0;
            oa[nt][2] *= corr1; oa[nt][3] *= corr1;
        }
        __syncthreads();  // all warps done reading Ks

        // ---- write P (tf32) into KP as Ps[k][q] ----
        #pragma unroll
        for (int nt = 0; nt < 8; nt++) {
            const int kk = nt*8 + tig*2;
            KP[(kk)  *AST + tw + gid]     = tf32r(sacc[nt][0]);
            KP[(kk+1)*AST + tw + gid]     = tf32r(sacc[nt][1]);
            KP[(kk)  *AST + tw + gid + 8] = tf32r(sacc[nt][2]);
            KP[(kk+1)*AST + tw + gid + 8] = tf32r(sacc[nt][3]);
        }
        __syncthreads();

        // ---- O += P V (M=q, N=d, K=k) ----
        #pragma unroll
        for (int ks = 0; ks < 8; ks++) {
            uint32_t a0 = __float_as_uint(KP[(ks*8+tig)*AST   + tw + gid]);
            uint32_t a1 = __float_as_uint(KP[(ks*8+tig)*AST   + tw + gid + 8]);
            uint32_t a2 = __float_as_uint(KP[(ks*8+4+tig)*AST + tw + gid]);
            uint32_t a3 = __float_as_uint(KP[(ks*8+4+tig)*AST + tw + gid + 8]);
            #pragma unroll
            for (int nt = 0; nt < 8; nt++) {
                uint32_t b0 = __float_as_uint(Vs[(ks*8+tig)*AST   + nt*8 + gid]);
                uint32_t b1 = __float_as_uint(Vs[(ks*8+4+tig)*AST + nt*8 + gid]);
                asm volatile(
                    "mma.sync.aligned.m16n8k8.row.col.f32.tf32.tf32.f32 "
                    "{%0,%1,%2,%3}, {%4,%5,%6,%7}, {%8,%9}, {%0,%1,%2,%3};"
                    : "+f"(oa[nt][0]), "+f"(oa[nt][1]),
                      "+f"(oa[nt][2]), "+f"(oa[nt][3])
                    : "r"(a0), "r"(a1), "r"(a2), "r"(a3), "r"(b0), "r"(b1));
            }
        }
        __syncthreads();
    }

    // ---- epilogue ----
    const float inv0 = 1.f / l0r, inv1 = 1.f / l1r;
    const size_t q0g = (size_t)(b*TQ + qt0 + tw + gid);
    #pragma unroll
    for (int nt = 0; nt < 8; nt++) {
        const int col = h*HD + nt*8 + tig*2;
        *(float2*)&out[q0g*DIMN + col] =
            make_float2(oa[nt][0]*inv0, oa[nt][1]*inv0);
        *(float2*)&out[(q0g + 8)*DIMN + col] =
            make_float2(oa[nt][2]*inv1, oa[nt][3]*inv1);
    }
}

// ---------------- row LayerNorm ----------------
__global__ __launch_bounds__(256) void ln_kernel(
    const float* __restrict__ in, const float* __restrict__ w,
    const float* __restrict__ bz, float* __restrict__ out)
{
    const int row = blockIdx.x, tid = threadIdx.x;
    const float* xr = in + (size_t)row * DIMN;
    float4 v = ((const float4*)xr)[tid];
    float s1 = v.x + v.y + v.z + v.w;
    float s2 = v.x*v.x + v.y*v.y + v.z*v.z + v.w*v.w;
    #pragma unroll
    for (int off = 16; off; off >>= 1) {
        s1 += __shfl_xor_sync(0xffffffffu, s1, off);
        s2 += __shfl_xor_sync(0xffffffffu, s2, off);
    }
    __shared__ float sh[16];
    const int warp = tid >> 5, lane = tid & 31;
    if (lane == 0) { sh[warp] = s1; sh[8 + warp] = s2; }
    __syncthreads();
    float t1 = 0.f, t2 = 0.f;
    #pragma unroll
    for (int wi = 0; wi < 8; wi++) { t1 += sh[wi]; t2 += sh[8 + wi]; }
    const float mean = t1 * (1.0f / DIMN);
    const float var  = t2 * (1.0f / DIMN) - mean * mean;
    const float rstd = rsqrtf(var + 1e-5f);
    float4 wv = ((const float4*)w)[tid];
    float4 bv = ((const float4*)bz)[tid];
    float4 ov;
    ov.x = (v.x - mean) * rstd * wv.x + bv.x;
    ov.y = (v.y - mean) * rstd * wv.y + bv.y;
    ov.z = (v.z - mean) * rstd * wv.z + bv.z;
    ov.w = (v.w - mean) * rstd * wv.w + bv.w;
    ((float4*)(out + (size_t)row * DIMN))[tid] = ov;
}

// ---------------- launcher ----------------
extern "C" void kernel_launch(void* const* d_in, const int* in_sizes, int n_in,
                              void* d_out, int out_size)
{
    const float* x    = (const float*)d_in[0];
    const float* h_a  = (const float*)d_in[1];
    const float* h_t  = (const float*)d_in[2];
    const float* p    = (const float*)d_in[3];
    const float* Wq   = (const float*)d_in[4];  const float* bq  = (const float*)d_in[5];
    const float* Wks  = (const float*)d_in[6];  const float* bks = (const float*)d_in[7];
    const float* Wvs  = (const float*)d_in[8];  const float* bvs = (const float*)d_in[9];
    const float* Wka  = (const float*)d_in[10]; const float* bka = (const float*)d_in[11];
    const float* Wva  = (const float*)d_in[12]; const float* bva = (const float*)d_in[13];
    const float* Wkt  = (const float*)d_in[14]; const float* bkt = (const float*)d_in[15];
    const float* Wvt  = (const float*)d_in[16]; const float* bvt = (const float*)d_in[17];
    const float* Wo   = (const float*)d_in[18]; const float* bo  = (const float*)d_in[19];
    const float* Wf   = (const float*)d_in[20]; const float* bf  = (const float*)d_in[21];
    const float* gating = (const float*)d_in[22];
    const float* ln_w = (const float*)d_in[23];
    const float* ln_b = (const float*)d_in[24];
    float* outp = (float*)d_out;

    float *Qt, *Kt, *Vv, *AO, *Y, *LN, *RC, *RS, *WTb;
    cudaGetSymbolAddress((void**)&Qt, g_Qt);
    cudaGetSymbolAddress((void**)&Kt, g_Kt);
    cudaGetSymbolAddress((void**)&Vv, g_V);
    cudaGetSymbolAddress((void**)&AO, g_AO);
    cudaGetSymbolAddress((void**)&Y,  g_Y);
    cudaGetSymbolAddress((void**)&LN, g_LN);
    cudaGetSymbolAddress((void**)&RC, g_RC);
    cudaGetSymbolAddress((void**)&RS, g_RS);
    cudaGetSymbolAddress((void**)&WTb, g_WT);

    const size_t WSZ = (size_t)DIMN * DIMN;
    float* WTq  = WTb + 0*WSZ;  float* WTks = WTb + 1*WSZ;  float* WTvs = WTb + 2*WSZ;
    float* WTka = WTb + 3*WSZ;  float* WTva = WTb + 4*WSZ;  float* WTkt = WTb + 5*WSZ;
    float* WTvt = WTb + 6*WSZ;  float* WTo  = WTb + 7*WSZ;  float* WTf  = WTb + 8*WSZ;

    const int smemb = SMEMF * 4;
    cudaFuncSetAttribute(tgemm<0,false,true ,false,false>, cudaFuncAttributeMaxDynamicSharedMemorySize, smemb);
    cudaFuncSetAttribute(tgemm<0,false,false,true ,false>, cudaFuncAttributeMaxDynamicSharedMemorySize, smemb);
    cudaFuncSetAttribute(tgemm<1,false,false,false,true >, cudaFuncAttributeMaxDynamicSharedMemorySize, smemb);
    cudaFuncSetAttribute(tgemm<2,true ,false,false,true >, cudaFuncAttributeMaxDynamicSharedMemorySize, smemb);
    cudaFuncSetAttribute(tgemm<2,false,false,false,true >, cudaFuncAttributeMaxDynamicSharedMemorySize, smemb);
    cudaFuncSetAttribute(attn_mma, cudaFuncAttributeMaxDynamicSharedMemorySize, ATT_SMEM);

    dim3 blk(256);
    dim3 tgrid(32, 32), tblk(32, 8);

    rope_tables<<<dim3(TQ/256, HD), 256>>>(RC, RS);
    wtrans<<<tgrid, tblk>>>(Wq,  WTq );
    wtrans<<<tgrid, tblk>>>(Wks, WTks);
    wtrans<<<tgrid, tblk>>>(Wvs, WTvs);
    wtrans<<<tgrid, tblk>>>(Wka, WTka);
    wtrans<<<tgrid, tblk>>>(Wva, WTva);
    wtrans<<<tgrid, tblk>>>(Wkt, WTkt);
    wtrans<<<tgrid, tblk>>>(Wvt, WTvt);
    wtrans<<<tgrid, tblk>>>(Wo,  WTo );
    wtrans<<<tgrid, tblk>>>(Wf,  WTf );

    // projections (concat KV via toff; RoPE fused for q & k_self; tf32-rounded outputs)
    tgemm<2,true ,false,false,true ><<<dim3(8,32), blk, smemb>>>(x,   WTq,  bq,  nullptr, RC, RS, Qt, 2048, TQ, 0);
    tgemm<2,true ,false,false,true ><<<dim3(8,32), blk, smemb>>>(x,   WTks, bks, nullptr, RC, RS, Kt, 2048, KV, 0);
    tgemm<1,false,false,false,true ><<<dim3(8,32), blk, smemb>>>(x,   WTvs, bvs, nullptr, nullptr, nullptr, Vv, 2048, KV, 0);
    tgemm<2,false,false,false,true ><<<dim3(8, 8), blk, smemb>>>(h_a, WTka, bka, nullptr, nullptr, nullptr, Kt,  512, KV, 2048);
    tgemm<2,false,false,false,true ><<<dim3(8, 4), blk, smemb>>>(p,   WTka, bka, nullptr, nullptr, nullptr, Kt,  256, KV, 2560);
    tgemm<1,false,false,false,true ><<<dim3(8, 8), blk, smemb>>>(h_a, WTva, bva, nullptr, nullptr, nullptr, Vv,  512, KV, 2048);
    tgemm<1,false,false,false,true ><<<dim3(8, 4), blk, smemb>>>(p,   WTva, bva, nullptr, nullptr, nullptr, Vv,  256, KV, 2560);
    tgemm<2,false,false,false,true ><<<dim3(8, 1), blk, smemb>>>(h_t, WTkt, bkt, nullptr, nullptr, nullptr, Kt,   64, KV, 2816);
    tgemm<1,false,false,false,true ><<<dim3(8, 1), blk, smemb>>>(h_t, WTvt, bvt, nullptr, nullptr, nullptr, Vv,   64, KV, 2816);

    // mma.sync flash attention over concatenated KV
    attn_mma<<<dim3(TQ/64, NH, BD), dim3(128), ATT_SMEM>>>(Qt, Kt, Vv, gating, AO);

    // out proj + residual, layernorm, FFN + relu
    tgemm<0,false,true ,false,false><<<dim3(8,32), blk, smemb>>>(AO, WTo, bo, x,       nullptr, nullptr, Y,    2048, 0, 0);
    ln_kernel<<<BD*TQ, 256>>>(Y, ln_w, ln_b, LN);
    tgemm<0,false,false,true ,false><<<dim3(8,32), blk, smemb>>>(LN, WTf, bf, nullptr, nullptr, nullptr, outp, 2048, 0, 0);
}

// round 6
// speedup vs baseline: 5.1275x; 1.1908x over previous
#include <cuda_runtime.h>
#include <cuda_fp16.h>
#include <math.h>
#include <math_constants.h>
#include <cstdint>

#define DIMN 1024
#define NH   16
#define HD   64
#define TQ   2048
#define KV   2880     // 2048 self + 768 adapter + 64 task
#define BD   2
#define TASK_OFF 2816

// ---------------- scratch (static device globals; no allocation) ----------------
__device__ __align__(16) __half g_Qt[BD*NH*TQ*HD];   // [b][h][t][d]
__device__ __align__(16) __half g_Kt[BD*NH*KV*HD];   // [b][h][k][d]  (concat: self|adapter|task)
__device__ __align__(16) __half g_V [BD*NH*HD*KV];   // [b][h][d][k]
__device__ __align__(16) float  g_AO[BD*TQ*DIMN];    // attention output (B,T,D)
__device__ __align__(16) float  g_Y [BD*TQ*DIMN];    // post-Wo + residual
__device__ __align__(16) float  g_LN[BD*TQ*DIMN];    // post-LN
__device__ __align__(16) float  g_RC[HD*TQ];         // rope cos [d][t]
__device__ __align__(16) float  g_RS[HD*TQ];         // rope sin [d][t]
__device__ __align__(16) __half g_WT[9u*DIMN*DIMN];  // transposed fp16 weights [n][k]

__device__ __forceinline__ uint32_t packh2(float x, float y) {
    __half2 h = __floats2half2_rn(x, y);
    return *reinterpret_cast<uint32_t*>(&h);
}
__device__ __forceinline__ uint32_t smem_u32(const void* p) {
    uint32_t a;
    asm("{ .reg .u64 t; cvta.to.shared.u64 t, %1; cvt.u32.u64 %0, t; }" : "=r"(a) : "l"(p));
    return a;
}
#define CP16(dst, src) \
    asm volatile("cp.async.cg.shared.global [%0], [%1], 16;" :: "r"(dst), "l"(src) : "memory")
#define CP_COMMIT() asm volatile("cp.async.commit_group;" ::: "memory")
#define CP_WAIT1()  asm volatile("cp.async.wait_group 1;" ::: "memory")
#define CP_WAIT0()  asm volatile("cp.async.wait_group 0;" ::: "memory")

#define MMA_F16(C, A0,A1,A2,A3, B0,B1) \
    asm volatile("mma.sync.aligned.m16n8k16.row.col.f32.f16.f16.f32 " \
        "{%0,%1,%2,%3}, {%4,%5,%6,%7}, {%8,%9}, {%0,%1,%2,%3};" \
        : "+f"((C)[0]), "+f"((C)[1]), "+f"((C)[2]), "+f"((C)[3]) \
        : "r"(A0), "r"(A1), "r"(A2), "r"(A3), "r"(B0), "r"(B1))

// ---------------- batched W transpose + fp16 convert: WT[n][k] = h(W[k][n]) ----------------
struct W9 { const float* w[9]; };
__global__ __launch_bounds__(256) void wtrans9(W9 ws, __half* __restrict__ WT) {
    __shared__ float tile[32][33];
    const float* W = ws.w[blockIdx.z];
    __half* O = WT + (size_t)blockIdx.z * DIMN * DIMN;
    const int x = threadIdx.x, y = threadIdx.y;
    const int n0 = blockIdx.x * 32, k0 = blockIdx.y * 32;
    #pragma unroll
    for (int j = 0; j < 4; j++)
        tile[y + 8*j][x] = W[(size_t)(k0 + y + 8*j) * DIMN + n0 + x];
    __syncthreads();
    #pragma unroll
    for (int j = 0; j < 4; j++)
        O[(size_t)(n0 + y + 8*j) * DIMN + k0 + x] = __float2half(tile[x][y + 8*j]);
}

// ======================= fp16 mma.sync GEMM, 128x128x32 tile =======================
// smem rows: 32 halfs (64B), 4 chunks of 8 halfs, chunk-XOR swizzle c' = c ^ ((row>>1)&3)
// MODE 0: fp32 [m][n] (+RESID/+RELU); MODE 1: half [bh][t][d] (+ROPE); MODE 2: half [bh][d][t]
template<int MODE, bool ROPE, bool RESID, bool RELU>
__global__ __launch_bounds__(256, 2) void tgemm(
    const float* __restrict__ A, const __half* __restrict__ WT,
    const float* __restrict__ bias, const float* __restrict__ resid,
    const float* __restrict__ Ctab, const float* __restrict__ Stab,
    void* __restrict__ outv, int T_A, int Lout, int toff)
{
    __shared__ __half As[2][128*32];
    __shared__ __half Bs[2][128*32];
    __shared__ float bias_s[128];
    const int tid = threadIdx.x;
    const int wid = tid >> 5, lid = tid & 31;
    const int gid = lid >> 2, tig = lid & 3;
    const int warp_m = wid & 3, warp_n = wid >> 2;
    const int m0 = blockIdx.y * 128, n0 = blockIdx.x * 128;
    if (tid < 32) *(float4*)&bias_s[tid*4] = *(const float4*)&bias[n0 + tid*4];

    // A fill mapping: row lr+32i, k-cols lkq*4..+3
    const int lr = tid >> 3, lkq = tid & 7;
    const int xa = (lr >> 1) & 3;
    const int aoff = (((lkq >> 1) ^ xa) << 3) + (lkq & 1) * 4;
    const float* Ap = A + (size_t)(m0 + lr) * DIMN + lkq * 4;
    // B fill mapping: row bn+64i, chunk bc
    const int bn = tid >> 2, bc = tid & 3;
    const int boff = ((bc ^ ((bn >> 1) & 3)) << 3);
    const __half* Wp = WT + (size_t)(n0 + bn) * DIMN + bc * 8;

    const int xg = (gid >> 1) & 3;

    float acc[2][8][4];
    #pragma unroll
    for (int mt = 0; mt < 2; mt++)
        #pragma unroll
        for (int nt = 0; nt < 8; nt++)
            #pragma unroll
            for (int c = 0; c < 4; c++) acc[mt][nt][c] = 0.f;

    // stage 0
    #pragma unroll
    for (int i = 0; i < 4; i++) {
        float4 v = *(const float4*)(Ap + (size_t)32*i*DIMN);
        uint2 u = make_uint2(packh2(v.x, v.y), packh2(v.z, v.w));
        *(uint2*)&As[0][(lr + 32*i)*32 + aoff] = u;
    }
    #pragma unroll
    for (int i = 0; i < 2; i++)
        *(uint4*)&Bs[0][(bn + 64*i)*32 + boff] = *(const uint4*)(Wp + (size_t)64*i*DIMN);
    __syncthreads();

    for (int kc = 0; kc < 32; kc++) {
        const int cur = kc & 1;
        float4 pa[4]; uint4 pb[2];
        if (kc < 31) {
            #pragma unroll
            for (int i = 0; i < 4; i++)
                pa[i] = *(const float4*)(Ap + (size_t)32*i*DIMN + (kc+1)*32);
            #pragma unroll
            for (int i = 0; i < 2; i++)
                pb[i] = *(const uint4*)(Wp + (size_t)64*i*DIMN + (kc+1)*32);
        }
        const __half* as_ = As[cur];
        const __half* bs_ = Bs[cur];
        #pragma unroll
        for (int ks = 0; ks < 2; ks++) {
            const int c0 = ((2*ks) ^ xg) << 3, c1 = ((2*ks + 1) ^ xg) << 3;
            uint32_t af[2][4], bf[8][2];
            #pragma unroll
            for (int mt = 0; mt < 2; mt++) {
                const int r0 = (warp_m*32 + mt*16 + gid)*32, r1 = r0 + 8*32;
                af[mt][0] = *(const uint32_t*)&as_[r0 + c0 + 2*tig];
                af[mt][1] = *(const uint32_t*)&as_[r1 + c0 + 2*tig];
                af[mt][2] = *(const uint32_t*)&as_[r0 + c1 + 2*tig];
                af[mt][3] = *(const uint32_t*)&as_[r1 + c1 + 2*tig];
            }
            #pragma unroll
            for (int nt = 0; nt < 8; nt++) {
                const int rn = (warp_n*64 + nt*8 + gid)*32;
                bf[nt][0] = *(const uint32_t*)&bs_[rn + c0 + 2*tig];
                bf[nt][1] = *(const uint32_t*)&bs_[rn + c1 + 2*tig];
            }
            #pragma unroll
            for (int mt = 0; mt < 2; mt++)
                #pragma unroll
                for (int nt = 0; nt < 8; nt++)
                    MMA_F16(acc[mt][nt], af[mt][0], af[mt][1], af[mt][2], af[mt][3],
                            bf[nt][0], bf[nt][1]);
        }
        if (kc < 31) {
            const int nxt = cur ^ 1;
            #pragma unroll
            for (int i = 0; i < 4; i++) {
                uint2 u = make_uint2(packh2(pa[i].x, pa[i].y), packh2(pa[i].z, pa[i].w));
                *(uint2*)&As[nxt][(lr + 32*i)*32 + aoff] = u;
            }
            #pragma unroll
            for (int i = 0; i < 2; i++)
                *(uint4*)&Bs[nxt][(bn + 64*i)*32 + boff] = pb[i];
        }
        __syncthreads();
    }

    // ---- epilogue ----
    #pragma unroll
    for (int mt = 0; mt < 2; mt++) {
        #pragma unroll
        for (int half_ = 0; half_ < 2; half_++) {
            const int m = m0 + warp_m*32 + mt*16 + gid + half_*8;
            const int t = m % T_A, bb = m / T_A;
            #pragma unroll
            for (int nt = 0; nt < 8; nt++) {
                const int nc = warp_n*64 + nt*8 + tig*2;
                const int n = n0 + nc;
                float c0 = acc[mt][nt][half_*2+0] + bias_s[nc];
                float c1 = acc[mt][nt][half_*2+1] + bias_s[nc+1];
                if (MODE == 0) {
                    float* out = (float*)outv;
                    float2 o = make_float2(c0, c1);
                    if (RESID) {
                        float2 rx = *(const float2*)&resid[(size_t)m*DIMN + n];
                        o.x += rx.x; o.y += rx.y;
                    }
                    if (RELU) { o.x = fmaxf(o.x, 0.f); o.y = fmaxf(o.y, 0.f); }
                    *(float2*)&out[(size_t)m*DIMN + n] = o;
                } else {
                    const int hh = n >> 6, d = n & 63;
                    if (ROPE) {
                        const float ce = Ctab[d*TQ + t],     se = Stab[d*TQ + t];
                        const float co = Ctab[(d+1)*TQ + t], so = Stab[(d+1)*TQ + t];
                        const float e = c0*ce - c1*se;
                        const float o = c1*co + c0*so;
                        c0 = e; c1 = o;
                    }
                    __half* out = (__half*)outv;
                    if (MODE == 1) {
                        __half2 hv = __floats2half2_rn(c0, c1);
                        *(__half2*)&out[((size_t)(bb*NH + hh)*Lout + toff + t)*HD + d] = hv;
                    } else {
                        const size_t rowb = (size_t)(bb*NH + hh)*HD;
                        out[(rowb + d)     * (size_t)Lout + toff + t] = __float2half(c0);
                        out[(rowb + d + 1) * (size_t)Lout + toff + t] = __float2half(c1);
                    }
                }
            }
        }
    }
}

// ---------------- rope tables [d][t] ----------------
__global__ void rope_tables(float* __restrict__ C, float* __restrict__ S) {
    const int t = blockIdx.x * 256 + threadIdx.x;
    const int d = blockIdx.y;
    const float C1 = 0.28782313662425572f;  // ln(10000)/32
    const float inv = expf(-(float)(d & 31) * C1);
    float se, ce;
    sincosf((float)t * inv, &se, &ce);
    C[d * TQ + t] = ce;
    S[d * TQ + t] = se;
}

// ======================= fp16 mma.sync flash attention =======================
// q-tile 128, 256 threads (8 warps x 16 q rows), KV tiles of 64, cp.async double-buffered.
// Layouts (half, row stride 72):
//   Qs[q][d] 128x72 | Ks[2][k][d] 64x72 | Vs[2][d][k] 64x72.  P stays in registers.
static constexpr int AQS = 0;                      // bytes
static constexpr int AKS = 128*72*2;               // 18432
static constexpr int AVS = AKS + 2*64*72*2;        // 36864
static constexpr int ATT_SMEM = AVS + 2*64*72*2;   // 55296

__global__ __launch_bounds__(256, 2) void attn_mma(
    const __half* __restrict__ Qt, const __half* __restrict__ Kt,
    const __half* __restrict__ Vv, const float* __restrict__ gate,
    float* __restrict__ out)
{
    extern __shared__ char smraw[];
    __half* Qs = (__half*)(smraw + AQS);
    __half* Ks0 = (__half*)(smraw + AKS);
    __half* Vs0 = (__half*)(smraw + AVS);
    const uint32_t sb = smem_u32(smraw);
    const int tid = threadIdx.x;
    const int wid = tid >> 5, lane = tid & 31;
    const int gid = lane >> 2, tig = lane & 3;
    const int tw = wid * 16;
    const int qt0 = blockIdx.x * 128;
    const int h = blockIdx.y, b = blockIdx.z, bh = b*NH + h;
    const float g = tanhf(gate[0]);

    const __half* qbase = Qt + (size_t)bh*TQ*HD + (size_t)qt0*HD;
    const __half* kbase = Kt + (size_t)bh*KV*HD;
    const __half* vbase = Vv + (size_t)bh*HD*KV;

    // issue Q tile (128 rows x 8 chunks) + KV tile 0 (64x8 each) in cp.async group 0
    {
        #pragma unroll
        for (int j = 0; j < 4; j++) {
            const int idx = tid + 256*j;
            const int r = idx >> 3, c = idx & 7;
            CP16(sb + AQS + r*144 + c*16, qbase + (size_t)r*HD + c*8);
        }
        #pragma unroll
        for (int j = 0; j < 4; j++) {
            const int idx = tid + 256*j;
            const int r = (idx >> 3) & 63, c = idx & 7;
            if (idx < 512) CP16(sb + AKS + r*144 + c*16, kbase + (size_t)r*HD + c*8);
            else           CP16(sb + AVS + r*144 + c*16, vbase + (size_t)r*KV + c*8);
        }
        CP_COMMIT();
    }

    float m0r = -CUDART_INF_F, m1r = -CUDART_INF_F, l0r = 0.f, l1r = 0.f;
    float oa[8][4];
    #pragma unroll
    for (int nt = 0; nt < 8; nt++)
        #pragma unroll
        for (int c = 0; c < 4; c++) oa[nt][c] = 0.f;

    for (int tk = 0; tk < KV/64; tk++) {
        const int cur = tk & 1;
        if (tk + 1 < KV/64) {
            const int nb = (tk + 1) & 1;
            const int k0n = (tk + 1) * 64;
            #pragma unroll
            for (int j = 0; j < 4; j++) {
                const int idx = tid + 256*j;
                const int r = (idx >> 3) & 63, c = idx & 7;
                if (idx < 512) CP16(sb + AKS + nb*9216 + r*144 + c*16,
                                    kbase + (size_t)(k0n + r)*HD + c*8);
                else           CP16(sb + AVS + nb*9216 + r*144 + c*16,
                                    vbase + (size_t)r*KV + k0n + c*8);
            }
            CP_COMMIT();
            CP_WAIT1();
        } else {
            CP_WAIT0();
        }
        __syncthreads();
        const __half* ks_ = Ks0 + cur*(64*72);
        const __half* vs_ = Vs0 + cur*(64*72);

        // ---- S = Q K^T (M=q16/warp, N=kv, K=d=64) ----
        float sacc[8][4];
        #pragma unroll
        for (int nt = 0; nt < 8; nt++)
            #pragma unroll
            for (int c = 0; c < 4; c++) sacc[nt][c] = 0.f;
        #pragma unroll
        for (int ks = 0; ks < 4; ks++) {
            const int kb = ks * 16;
            const uint32_t a0 = *(const uint32_t*)&Qs[(tw+gid)*72   + kb + 2*tig];
            const uint32_t a1 = *(const uint32_t*)&Qs[(tw+gid+8)*72 + kb + 2*tig];
            const uint32_t a2 = *(const uint32_t*)&Qs[(tw+gid)*72   + kb + 8 + 2*tig];
            const uint32_t a3 = *(const uint32_t*)&Qs[(tw+gid+8)*72 + kb + 8 + 2*tig];
            #pragma unroll
            for (int nt = 0; nt < 8; nt++) {
                const uint32_t b0 = *(const uint32_t*)&ks_[(nt*8+gid)*72 + kb + 2*tig];
                const uint32_t b1 = *(const uint32_t*)&ks_[(nt*8+gid)*72 + kb + 8 + 2*tig];
                MMA_F16(sacc[nt], a0, a1, a2, a3, b0, b1);
            }
        }

        // ---- online softmax (rows tw+gid, tw+gid+8) ----
        const float sc = (tk == TASK_OFF/64) ? 0.125f * g : 0.125f;
        float mx0 = -CUDART_INF_F, mx1 = -CUDART_INF_F;
        #pragma unroll
        for (int nt = 0; nt < 8; nt++) {
            sacc[nt][0] *= sc; sacc[nt][1] *= sc; sacc[nt][2] *= sc; sacc[nt][3] *= sc;
            mx0 = fmaxf(mx0, fmaxf(sacc[nt][0], sacc[nt][1]));
            mx1 = fmaxf(mx1, fmaxf(sacc[nt][2], sacc[nt][3]));
        }
        #pragma unroll
        for (int off = 1; off < 4; off <<= 1) {
            mx0 = fmaxf(mx0, __shfl_xor_sync(0xffffffffu, mx0, off));
            mx1 = fmaxf(mx1, __shfl_xor_sync(0xffffffffu, mx1, off));
        }
        const float nm0 = fmaxf(m0r, mx0), nm1 = fmaxf(m1r, mx1);
        const float corr0 = __expf(m0r - nm0), corr1 = __expf(m1r - nm1);
        m0r = nm0; m1r = nm1;
        float rs0 = 0.f, rs1 = 0.f;
        #pragma unroll
        for (int nt = 0; nt < 8; nt++) {
            sacc[nt][0] = __expf(sacc[nt][0] - nm0);
            sacc[nt][1] = __expf(sacc[nt][1] - nm0);
            sacc[nt][2] = __expf(sacc[nt][2] - nm1);
            sacc[nt][3] = __expf(sacc[nt][3] - nm1);
            rs0 += sacc[nt][0] + sacc[nt][1];
            rs1 += sacc[nt][2] + sacc[nt][3];
        }
        #pragma unroll
        for (int off = 1; off < 4; off <<= 1) {
            rs0 += __shfl_xor_sync(0xffffffffu, rs0, off);
            rs1 += __shfl_xor_sync(0xffffffffu, rs1, off);
        }
        l0r = l0r * corr0 + rs0;
        l1r = l1r * corr1 + rs1;
        #pragma unroll
        for (int nt = 0; nt < 8; nt++) {
            oa[nt][0] *= corr0; oa[nt][1] *= corr0;
            oa[nt][2] *= corr1; oa[nt][3] *= corr1;
        }

        // ---- P (registers, fp16) : S-mma C frag == PV A frag ----
        uint32_t pf[4][4];
        #pragma unroll
        for (int j = 0; j < 4; j++) {
            pf[j][0] = packh2(sacc[2*j][0],   sacc[2*j][1]);
            pf[j][1] = packh2(sacc[2*j][2],   sacc[2*j][3]);
            pf[j][2] = packh2(sacc[2*j+1][0], sacc[2*j+1][1]);
            pf[j][3] = packh2(sacc[2*j+1][2], sacc[2*j+1][3]);
        }

        // ---- O += P V (M=q, N=d, K=kv=64) ----
        #pragma unroll
        for (int j = 0; j < 4; j++) {
            const int kb = j * 16;
            #pragma unroll
            for (int nt = 0; nt < 8; nt++) {
                const uint32_t b0 = *(const uint32_t*)&vs_[(nt*8+gid)*72 + kb + 2*tig];
                const uint32_t b1 = *(const uint32_t*)&vs_[(nt*8+gid)*72 + kb + 8 + 2*tig];
                MMA_F16(oa[nt], pf[j][0], pf[j][1], pf[j][2], pf[j][3], b0, b1);
            }
        }
        __syncthreads();
    }

    // ---- epilogue (fp32 AO) ----
    const float inv0 = 1.f / l0r, inv1 = 1.f / l1r;
    const size_t q0g = (size_t)(b*TQ + qt0 + tw + gid);
    #pragma unroll
    for (int nt = 0; nt < 8; nt++) {
        const int col = h*HD + nt*8 + tig*2;
        *(float2*)&out[q0g*DIMN + col] = make_float2(oa[nt][0]*inv0, oa[nt][1]*inv0);
        *(float2*)&out[(q0g + 8)*DIMN + col] = make_float2(oa[nt][2]*inv1, oa[nt][3]*inv1);
    }
}

// ---------------- row LayerNorm ----------------
__global__ __launch_bounds__(256) void ln_kernel(
    const float* __restrict__ in, const float* __restrict__ w,
    const float* __restrict__ bz, float* __restrict__ out)
{
    const int row = blockIdx.x, tid = threadIdx.x;
    const float* xr = in + (size_t)row * DIMN;
    float4 v = ((const float4*)xr)[tid];
    float s1 = v.x + v.y + v.z + v.w;
    float s2 = v.x*v.x + v.y*v.y + v.z*v.z + v.w*v.w;
    #pragma unroll
    for (int off = 16; off; off >>= 1) {
        s1 += __shfl_xor_sync(0xffffffffu, s1, off);
        s2 += __shfl_xor_sync(0xffffffffu, s2, off);
    }
    __shared__ float sh[16];
    const int warp = tid >> 5, lane = tid & 31;
    if (lane == 0) { sh[warp] = s1; sh[8 + warp] = s2; }
    __syncthreads();
    float t1 = 0.f, t2 = 0.f;
    #pragma unroll
    for (int wi = 0; wi < 8; wi++) { t1 += sh[wi]; t2 += sh[8 + wi]; }
    const float mean = t1 * (1.0f / DIMN);
    const float var  = t2 * (1.0f / DIMN) - mean * mean;
    const float rstd = rsqrtf(var + 1e-5f);
    float4 wv = ((const float4*)w)[tid];
    float4 bv = ((const float4*)bz)[tid];
    float4 ov;
    ov.x = (v.x - mean) * rstd * wv.x + bv.x;
    ov.y = (v.y - mean) * rstd * wv.y + bv.y;
    ov.z = (v.z - mean) * rstd * wv.z + bv.z;
    ov.w = (v.w - mean) * rstd * wv.w + bv.w;
    ((float4*)(out + (size_t)row * DIMN))[tid] = ov;
}

// ---------------- launcher ----------------
extern "C" void kernel_launch(void* const* d_in, const int* in_sizes, int n_in,
                              void* d_out, int out_size)
{
    const float* x    = (const float*)d_in[0];
    const float* h_a  = (const float*)d_in[1];
    const float* h_t  = (const float*)d_in[2];
    const float* p    = (const float*)d_in[3];
    const float* Wq   = (const float*)d_in[4];  const float* bq  = (const float*)d_in[5];
    const float* Wks  = (const float*)d_in[6];  const float* bks = (const float*)d_in[7];
    const float* Wvs  = (const float*)d_in[8];  const float* bvs = (const float*)d_in[9];
    const float* Wka  = (const float*)d_in[10]; const float* bka = (const float*)d_in[11];
    const float* Wva  = (const float*)d_in[12]; const float* bva = (const float*)d_in[13];
    const float* Wkt  = (const float*)d_in[14]; const float* bkt = (const float*)d_in[15];
    const float* Wvt  = (const float*)d_in[16]; const float* bvt = (const float*)d_in[17];
    const float* Wo   = (const float*)d_in[18]; const float* bo  = (const float*)d_in[19];
    const float* Wf   = (const float*)d_in[20]; const float* bf  = (const float*)d_in[21];
    const float* gating = (const float*)d_in[22];
    const float* ln_w = (const float*)d_in[23];
    const float* ln_b = (const float*)d_in[24];
    float* outp = (float*)d_out;

    __half *Qt, *Kt, *Vv, *WTb;
    float *AO, *Y, *LN, *RC, *RS;
    cudaGetSymbolAddress((void**)&Qt, g_Qt);
    cudaGetSymbolAddress((void**)&Kt, g_Kt);
    cudaGetSymbolAddress((void**)&Vv, g_V);
    cudaGetSymbolAddress((void**)&AO, g_AO);
    cudaGetSymbolAddress((void**)&Y,  g_Y);
    cudaGetSymbolAddress((void**)&LN, g_LN);
    cudaGetSymbolAddress((void**)&RC, g_RC);
    cudaGetSymbolAddress((void**)&RS, g_RS);
    cudaGetSymbolAddress((void**)&WTb, g_WT);

    const size_t WSZ = (size_t)DIMN * DIMN;
    __half* WTq  = WTb + 0*WSZ;  __half* WTks = WTb + 1*WSZ;  __half* WTvs = WTb + 2*WSZ;
    __half* WTka = WTb + 3*WSZ;  __half* WTva = WTb + 4*WSZ;  __half* WTkt = WTb + 5*WSZ;
    __half* WTvt = WTb + 6*WSZ;  __half* WTo  = WTb + 7*WSZ;  __half* WTf  = WTb + 8*WSZ;

    cudaFuncSetAttribute(attn_mma, cudaFuncAttributeMaxDynamicSharedMemorySize, ATT_SMEM);

    dim3 blk(256);
    rope_tables<<<dim3(TQ/256, HD), 256>>>(RC, RS);
    W9 ws;
    ws.w[0]=Wq; ws.w[1]=Wks; ws.w[2]=Wvs; ws.w[3]=Wka; ws.w[4]=Wva;
    ws.w[5]=Wkt; ws.w[6]=Wvt; ws.w[7]=Wo; ws.w[8]=Wf;
    wtrans9<<<dim3(32, 32, 9), dim3(32, 8)>>>(ws, WTb);

    // projections (concat KV via toff; RoPE fused for q & k_self; half outputs)
    tgemm<1,true ,false,false><<<dim3(8,32), blk>>>(x,   WTq,  bq,  nullptr, RC, RS, Qt, 2048, TQ, 0);
    tgemm<1,true ,false,false><<<dim3(8,32), blk>>>(x,   WTks, bks, nullptr, RC, RS, Kt, 2048, KV, 0);
    tgemm<2,false,false,false><<<dim3(8,32), blk>>>(x,   WTvs, bvs, nullptr, nullptr, nullptr, Vv, 2048, KV, 0);
    tgemm<1,false,false,false><<<dim3(8, 8), blk>>>(h_a, WTka, bka, nullptr, nullptr, nullptr, Kt,  512, KV, 2048);
    tgemm<1,false,false,false><<<dim3(8, 4), blk>>>(p,   WTka, bka, nullptr, nullptr, nullptr, Kt,  256, KV, 2560);
    tgemm<2,false,false,false><<<dim3(8, 8), blk>>>(h_a, WTva, bva, nullptr, nullptr, nullptr, Vv,  512, KV, 2048);
    tgemm<2,false,false,false><<<dim3(8, 4), blk>>>(p,   WTva, bva, nullptr, nullptr, nullptr, Vv,  256, KV, 2560);
    tgemm<1,false,false,false><<<dim3(8, 1), blk>>>(h_t, WTkt, bkt, nullptr, nullptr, nullptr, Kt,   64, KV, 2816);
    tgemm<2,false,false,false><<<dim3(8, 1), blk>>>(h_t, WTvt, bvt, nullptr, nullptr, nullptr, Vv,   64, KV, 2816);

    // fp16 flash attention over concatenated KV
    attn_mma<<<dim3(TQ/128, NH, BD), dim3(256), ATT_SMEM>>>(Qt, Kt, Vv, gating, AO);

    // out proj + residual, layernorm, FFN + relu
    tgemm<0,false,true ,false><<<dim3(8,32), blk>>>(AO, WTo, bo, x,       nullptr, nullptr, Y,    2048, 0, 0);
    ln_kernel<<<BD*TQ, 256>>>(Y, ln_w, ln_b, LN);
    tgemm<0,false,false,true ><<<dim3(8,32), blk>>>(LN, WTf, bf, nullptr, nullptr, nullptr, outp, 2048, 0, 0);
}

// round 7
// speedup vs baseline: 8.8846x; 1.7327x over previous
#include <cuda_runtime.h>
#include <cuda_fp16.h>
#include <math.h>
#include <math_constants.h>
#include <cstdint>

#define DIMN 1024
#define NH   16
#define HD   64
#define TQ   2048
#define KV   2880     // 2048 self + 768 adapter + 64 task
#define BD   2
#define TASK_OFF 2816

// ---------------- scratch (static device globals; no allocation) ----------------
__device__ __align__(16) __half g_Qt [BD*NH*TQ*HD];   // [b][h][t][d]
__device__ __align__(16) __half g_Kt [BD*NH*KV*HD];   // [b][h][k][d]
__device__ __align__(16) __half g_V  [BD*NH*HD*KV];   // [b][h][d][k]
__device__ __align__(16) __half g_AOh[BD*TQ*DIMN];    // attention output (half)
__device__ __align__(16) float  g_Y  [BD*TQ*DIMN];    // post-Wo + residual (fp32)
__device__ __align__(16) __half g_LNh[BD*TQ*DIMN];    // post-LN (half)
__device__ __align__(16) float  g_RC [HD*TQ];         // rope cos [d][t]
__device__ __align__(16) float  g_RS [HD*TQ];         // rope sin [d][t]
__device__ __align__(16) __half g_WT [9u*DIMN*DIMN];  // transposed fp16 weights [n][k]
__device__ __align__(16) __half g_XH [6u*1024*1024];  // halved activations

__device__ __forceinline__ uint32_t packh2(float x, float y) {
    __half2 h = __floats2half2_rn(x, y);
    return *reinterpret_cast<uint32_t*>(&h);
}
__device__ __forceinline__ uint32_t smem_u32(const void* p) {
    uint32_t a;
    asm("{ .reg .u64 t; cvta.to.shared.u64 t, %1; cvt.u32.u64 %0, t; }" : "=r"(a) : "l"(p));
    return a;
}
#define CP16(dst, src) \
    asm volatile("cp.async.cg.shared.global [%0], [%1], 16;" :: "r"(dst), "l"(src) : "memory")
#define CP_COMMIT() asm volatile("cp.async.commit_group;" ::: "memory")
#define CP_WAIT1()  asm volatile("cp.async.wait_group 1;" ::: "memory")
#define CP_WAIT0()  asm volatile("cp.async.wait_group 0;" ::: "memory")

#define MMA_F16(C, A0,A1,A2,A3, B0,B1) \
    asm volatile("mma.sync.aligned.m16n8k16.row.col.f32.f16.f16.f32 " \
        "{%0,%1,%2,%3}, {%4,%5,%6,%7}, {%8,%9}, {%0,%1,%2,%3};" \
        : "+f"((C)[0]), "+f"((C)[1]), "+f"((C)[2]), "+f"((C)[3]) \
        : "r"(A0), "r"(A1), "r"(A2), "r"(A3), "r"(B0), "r"(B1))

#define LDSM4(R0,R1,R2,R3, addr) \
    asm volatile("ldmatrix.sync.aligned.m8n8.x4.shared.b16 {%0,%1,%2,%3}, [%4];" \
        : "=r"(R0), "=r"(R1), "=r"(R2), "=r"(R3) : "r"(addr))

// ---------------- f32 -> f16 convert (activations) ----------------
__global__ __launch_bounds__(256) void f2h(const float* __restrict__ in,
                                           __half* __restrict__ out) {
    const size_t i = ((size_t)blockIdx.x * 256 + threadIdx.x) * 8;
    float4 a = *(const float4*)(in + i);
    float4 b = *(const float4*)(in + i + 4);
    uint4 u = make_uint4(packh2(a.x, a.y), packh2(a.z, a.w),
                         packh2(b.x, b.y), packh2(b.z, b.w));
    *(uint4*)(out + i) = u;
}

// ---------------- batched W transpose + fp16 convert: WT[n][k] = h(W[k][n]) ----------------
struct W9 { const float* w[9]; };
__global__ __launch_bounds__(256) void wtrans9(W9 ws, __half* __restrict__ WT) {
    __shared__ float tile[32][33];
    const float* W = ws.w[blockIdx.z];
    __half* O = WT + (size_t)blockIdx.z * DIMN * DIMN;
    const int x = threadIdx.x, y = threadIdx.y;
    const int n0 = blockIdx.x * 32, k0 = blockIdx.y * 32;
    #pragma unroll
    for (int j = 0; j < 4; j++)
        tile[y + 8*j][x] = W[(size_t)(k0 + y + 8*j) * DIMN + n0 + x];
    __syncthreads();
    #pragma unroll
    for (int j = 0; j < 4; j++)
        O[(size_t)(n0 + y + 8*j) * DIMN + k0 + x] = __float2half(tile[x][y + 8*j]);
}

// ======================= fp16 GEMM: ldmatrix + 3-stage cp.async =======================
// Tile 128x128x32. smem rows 32 halfs (64B), chunk-XOR swizzle c' = c ^ ((row>>1)&3).
// MODE 0: fp32 [m][n] (+RESID/+RELU); MODE 1: half [bh][t][d] (+ROPE); MODE 2: half [bh][d][t]
template<int MODE, bool ROPE, bool RESID, bool RELU>
__global__ __launch_bounds__(256, 2) void tgemm(
    const __half* __restrict__ A, const __half* __restrict__ WT,
    const float* __restrict__ bias, const float* __restrict__ resid,
    const float* __restrict__ Ctab, const float* __restrict__ Stab,
    void* __restrict__ outv, int T_A, int Lout, int toff)
{
    __shared__ __half As[3][128*32];
    __shared__ __half Bs[3][128*32];
    __shared__ float bias_s[128];
    const int tid = threadIdx.x;
    const int wid = tid >> 5, lane = tid & 31;
    const int gid = lane >> 2, tig = lane & 3;
    const int warp_m = wid & 3, warp_n = wid >> 2;
    const int m0 = blockIdx.y * 128, n0 = blockIdx.x * 128;
    if (tid < 32) *(float4*)&bias_s[tid*4] = *(const float4*)&bias[n0 + tid*4];

    const uint32_t sbA = smem_u32(As), sbB = smem_u32(Bs);
    const int fr = tid >> 2, fc = tid & 3;   // fill: rows fr, fr+64; chunk fc

    auto issue = [&](int st, int kc) {
        #pragma unroll
        for (int j = 0; j < 2; j++) {
            const int row = fr + 64*j;
            const int off = (row*32 + ((fc ^ ((row >> 1) & 3)) << 3)) * 2;
            CP16(sbA + st*8192 + off, A  + (size_t)(m0 + row)*DIMN + kc*32 + fc*8);
            CP16(sbB + st*8192 + off, WT + (size_t)(n0 + row)*DIMN + kc*32 + fc*8);
        }
        CP_COMMIT();
    };
    issue(0, 0);
    issue(1, 1);

    // fragment lane mappings
    const int a_lrow = (lane & 7) + ((lane >> 3) & 1) * 8;
    const int a_cs   = (lane >> 4) & 1;
    const int b_lrow = (lane & 7) + ((lane >> 4) & 1) * 8;
    const int b_cs   = (lane >> 3) & 1;
    int rowA[2], xrA[2], rowB[4], xrB[4];
    #pragma unroll
    for (int mt = 0; mt < 2; mt++) {
        rowA[mt] = warp_m*32 + mt*16 + a_lrow;
        xrA[mt] = (rowA[mt] >> 1) & 3;
    }
    #pragma unroll
    for (int np = 0; np < 4; np++) {
        rowB[np] = warp_n*64 + np*16 + b_lrow;
        xrB[np] = (rowB[np] >> 1) & 3;
    }

    float acc[2][8][4];
    #pragma unroll
    for (int mt = 0; mt < 2; mt++)
        #pragma unroll
        for (int nt = 0; nt < 8; nt++)
            #pragma unroll
            for (int c = 0; c < 4; c++) acc[mt][nt][c] = 0.f;

    for (int kc = 0; kc < 32; kc++) {
        const int cur = kc % 3;
        if (kc < 31) CP_WAIT1(); else CP_WAIT0();
        __syncthreads();
        if (kc + 2 < 32) issue((kc + 2) % 3, kc + 2);
        const uint32_t aB = sbA + cur*8192;
        const uint32_t bB = sbB + cur*8192;
        #pragma unroll
        for (int ks = 0; ks < 2; ks++) {
            uint32_t af[2][4], bf[4][4];
            #pragma unroll
            for (int mt = 0; mt < 2; mt++) {
                const int c = (2*ks + a_cs) ^ xrA[mt];
                LDSM4(af[mt][0], af[mt][1], af[mt][2], af[mt][3],
                      aB + (rowA[mt]*32 + (c << 3)) * 2);
            }
            #pragma unroll
            for (int np = 0; np < 4; np++) {
                const int c = (2*ks + b_cs) ^ xrB[np];
                LDSM4(bf[np][0], bf[np][1], bf[np][2], bf[np][3],
                      bB + (rowB[np]*32 + (c << 3)) * 2);
            }
            #pragma unroll
            for (int mt = 0; mt < 2; mt++)
                #pragma unroll
                for (int np = 0; np < 4; np++) {
                    MMA_F16(acc[mt][2*np],   af[mt][0], af[mt][1], af[mt][2], af[mt][3],
                            bf[np][0], bf[np][1]);
                    MMA_F16(acc[mt][2*np+1], af[mt][0], af[mt][1], af[mt][2], af[mt][3],
                            bf[np][2], bf[np][3]);
                }
        }
    }

    // ---- epilogue ----
    #pragma unroll
    for (int mt = 0; mt < 2; mt++) {
        #pragma unroll
        for (int half_ = 0; half_ < 2; half_++) {
            const int m = m0 + warp_m*32 + mt*16 + gid + half_*8;
            const int t = m % T_A, bb = m / T_A;
            #pragma unroll
            for (int nt = 0; nt < 8; nt++) {
                const int nc = warp_n*64 + nt*8 + tig*2;
                const int n = n0 + nc;
                float c0 = acc[mt][nt][half_*2+0] + bias_s[nc];
                float c1 = acc[mt][nt][half_*2+1] + bias_s[nc+1];
                if (MODE == 0) {
                    float* out = (float*)outv;
                    float2 o = make_float2(c0, c1);
                    if (RESID) {
                        float2 rx = *(const float2*)&resid[(size_t)m*DIMN + n];
                        o.x += rx.x; o.y += rx.y;
                    }
                    if (RELU) { o.x = fmaxf(o.x, 0.f); o.y = fmaxf(o.y, 0.f); }
                    *(float2*)&out[(size_t)m*DIMN + n] = o;
                } else {
                    const int hh = n >> 6, d = n & 63;
                    if (ROPE) {
                        const float ce = Ctab[d*TQ + t],     se = Stab[d*TQ + t];
                        const float co = Ctab[(d+1)*TQ + t], so = Stab[(d+1)*TQ + t];
                        const float e = c0*ce - c1*se;
                        const float o = c1*co + c0*so;
                        c0 = e; c1 = o;
                    }
                    __half* out = (__half*)outv;
                    if (MODE == 1) {
                        __half2 hv = __floats2half2_rn(c0, c1);
                        *(__half2*)&out[((size_t)(bb*NH + hh)*Lout + toff + t)*HD + d] = hv;
                    } else {
                        const size_t rowb = (size_t)(bb*NH + hh)*HD;
                        out[(rowb + d)     * (size_t)Lout + toff + t] = __float2half(c0);
                        out[(rowb + d + 1) * (size_t)Lout + toff + t] = __float2half(c1);
                    }
                }
            }
        }
    }
}

// ---------------- rope tables [d][t] ----------------
__global__ void rope_tables(float* __restrict__ C, float* __restrict__ S) {
    const int t = blockIdx.x * 256 + threadIdx.x;
    const int d = blockIdx.y;
    const float C1 = 0.28782313662425572f;  // ln(10000)/32
    const float inv = expf(-(float)(d & 31) * C1);
    float se, ce;
    sincosf((float)t * inv, &se, &ce);
    C[d * TQ + t] = ce;
    S[d * TQ + t] = se;
}

// ======================= fp16 flash attention: ldmatrix + hoisted Q =======================
// q-tile 128, 256 threads (8 warps x 16 q rows), KV tiles of 64, cp.async double-buffered.
// Layouts (half, row stride 72): Qs[q][d] 128x72 | Ks[2][k][d] 64x72 | Vs[2][d][k] 64x72.
static constexpr int AQS = 0;
static constexpr int AKS = 128*72*2;               // 18432
static constexpr int AVS = AKS + 2*64*72*2;        // 36864
static constexpr int ATT_SMEM = AVS + 2*64*72*2;   // 55296
static constexpr int NTILE = KV/64;                // 45

__global__ __launch_bounds__(256, 2) void attn_mma(
    const __half* __restrict__ Qt, const __half* __restrict__ Kt,
    const __half* __restrict__ Vv, const float* __restrict__ gate,
    __half* __restrict__ out)
{
    extern __shared__ char smraw[];
    const uint32_t sb = smem_u32(smraw);
    const int tid = threadIdx.x;
    const int wid = tid >> 5, lane = tid & 31;
    const int gid = lane >> 2, tig = lane & 3;
    const int tw = wid * 16;
    const int qt0 = blockIdx.x * 128;
    const int h = blockIdx.y, b = blockIdx.z, bh = b*NH + h;
    const float g = tanhf(gate[0]);

    const __half* qbase = Qt + (size_t)bh*TQ*HD + (size_t)qt0*HD;
    const __half* kbase = Kt + (size_t)bh*KV*HD;
    const __half* vbase = Vv + (size_t)bh*HD*KV;

    // group 0: Q tile (128 x 8 chunks)
    #pragma unroll
    for (int j = 0; j < 4; j++) {
        const int idx = tid + 256*j;
        const int r = idx >> 3, c = idx & 7;
        CP16(sb + AQS + r*144 + c*16, qbase + (size_t)r*HD + c*8);
    }
    CP_COMMIT();
    // group 1: KV tile 0
    #pragma unroll
    for (int j = 0; j < 4; j++) {
        const int idx = tid + 256*j;
        const int r = (idx >> 3) & 63, c = idx & 7;
        if (idx < 512) CP16(sb + AKS + r*144 + c*16, kbase + (size_t)r*HD + c*8);
        else           CP16(sb + AVS + r*144 + c*16, vbase + (size_t)r*KV + c*8);
    }
    CP_COMMIT();

    // wait for Q, hoist Q fragments into registers (loop-invariant)
    CP_WAIT1();
    __syncthreads();
    uint32_t qf[4][4];
    {
        const int rowQ = tw + (lane & 7) + ((lane >> 3) & 1) * 8;
        const int qcs  = (lane >> 4) & 1;
        #pragma unroll
        for (int ks = 0; ks < 4; ks++)
            LDSM4(qf[ks][0], qf[ks][1], qf[ks][2], qf[ks][3],
                  sb + AQS + rowQ*144 + ks*32 + qcs*16);
    }

    // K/V fragment lane mapping (rows kv or d, stride 144B)
    const int kv_lrow = (lane & 7) + ((lane >> 4) & 1) * 8;
    const int kv_cs16 = ((lane >> 3) & 1) * 16;
    int rowKVb[4];
    #pragma unroll
    for (int np = 0; np < 4; np++) rowKVb[np] = (np*16 + kv_lrow) * 144;

    float m0r = -CUDART_INF_F, m1r = -CUDART_INF_F, l0r = 0.f, l1r = 0.f;
    float oa[8][4];
    #pragma unroll
    for (int nt = 0; nt < 8; nt++)
        #pragma unroll
        for (int c = 0; c < 4; c++) oa[nt][c] = 0.f;

    for (int tk = 0; tk < NTILE; tk++) {
        const int cur = tk & 1;
        if (tk + 1 < NTILE) {
            const int nb = (tk + 1) & 1;
            const int k0n = (tk + 1) * 64;
            #pragma unroll
            for (int j = 0; j < 4; j++) {
                const int idx = tid + 256*j;
                const int r = (idx >> 3) & 63, c = idx & 7;
                if (idx < 512) CP16(sb + AKS + nb*9216 + r*144 + c*16,
                                    kbase + (size_t)(k0n + r)*HD + c*8);
                else           CP16(sb + AVS + nb*9216 + r*144 + c*16,
                                    vbase + (size_t)r*KV + k0n + c*8);
            }
            CP_COMMIT();
            CP_WAIT1();
        } else {
            CP_WAIT0();
        }
        __syncthreads();
        const uint32_t kB = sb + AKS + cur*9216;
        const uint32_t vB = sb + AVS + cur*9216;

        // ---- S = Q K^T ----
        float sacc[8][4];
        #pragma unroll
        for (int nt = 0; nt < 8; nt++)
            #pragma unroll
            for (int c = 0; c < 4; c++) sacc[nt][c] = 0.f;
        #pragma unroll
        for (int ks = 0; ks < 4; ks++) {
            #pragma unroll
            for (int np = 0; np < 4; np++) {
                uint32_t kf0, kf1, kf2, kf3;
                LDSM4(kf0, kf1, kf2, kf3, kB + rowKVb[np] + ks*32 + kv_cs16);
                MMA_F16(sacc[2*np],   qf[ks][0], qf[ks][1], qf[ks][2], qf[ks][3], kf0, kf1);
                MMA_F16(sacc[2*np+1], qf[ks][0], qf[ks][1], qf[ks][2], qf[ks][3], kf2, kf3);
            }
        }

        // ---- online softmax (rows tw+gid, tw+gid+8) ----
        const float sc = (tk == TASK_OFF/64) ? 0.125f * g : 0.125f;
        float mx0 = -CUDART_INF_F, mx1 = -CUDART_INF_F;
        #pragma unroll
        for (int nt = 0; nt < 8; nt++) {
            sacc[nt][0] *= sc; sacc[nt][1] *= sc; sacc[nt][2] *= sc; sacc[nt][3] *= sc;
            mx0 = fmaxf(mx0, fmaxf(sacc[nt][0], sacc[nt][1]));
            mx1 = fmaxf(mx1, fmaxf(sacc[nt][2], sacc[nt][3]));
        }
        #pragma unroll
        for (int off = 1; off < 4; off <<= 1) {
            mx0 = fmaxf(mx0, __shfl_xor_sync(0xffffffffu, mx0, off));
            mx1 = fmaxf(mx1, __shfl_xor_sync(0xffffffffu, mx1, off));
        }
        const float nm0 = fmaxf(m0r, mx0), nm1 = fmaxf(m1r, mx1);
        const float corr0 = __expf(m0r - nm0), corr1 = __expf(m1r - nm1);
        m0r = nm0; m1r = nm1;
        float rs0 = 0.f, rs1 = 0.f;
        #pragma unroll
        for (int nt = 0; nt < 8; nt++) {
            sacc[nt][0] = __expf(sacc[nt][0] - nm0);
            sacc[nt][1] = __expf(sacc[nt][1] - nm0);
            sacc[nt][2] = __expf(sacc[nt][2] - nm1);
            sacc[nt][3] = __expf(sacc[nt][3] - nm1);
            rs0 += sacc[nt][0] + sacc[nt][1];
            rs1 += sacc[nt][2] + sacc[nt][3];
        }
        #pragma unroll
        for (int off = 1; off < 4; off <<= 1) {
            rs0 += __shfl_xor_sync(0xffffffffu, rs0, off);
            rs1 += __shfl_xor_sync(0xffffffffu, rs1, off);
        }
        l0r = l0r * corr0 + rs0;
        l1r = l1r * corr1 + rs1;
        #pragma unroll
        for (int nt = 0; nt < 8; nt++) {
            oa[nt][0] *= corr0; oa[nt][1] *= corr0;
            oa[nt][2] *= corr1; oa[nt][3] *= corr1;
        }

        // ---- P in registers (S C-frag == PV A-frag) ----
        uint32_t pf[4][4];
        #pragma unroll
        for (int j = 0; j < 4; j++) {
            pf[j][0] = packh2(sacc[2*j][0],   sacc[2*j][1]);
            pf[j][1] = packh2(sacc[2*j][2],   sacc[2*j][3]);
            pf[j][2] = packh2(sacc[2*j+1][0], sacc[2*j+1][1]);
            pf[j][3] = packh2(sacc[2*j+1][2], sacc[2*j+1][3]);
        }

        // ---- O += P V ----
        #pragma unroll
        for (int j = 0; j < 4; j++) {
            #pragma unroll
            for (int np = 0; np < 4; np++) {
                uint32_t vf0, vf1, vf2, vf3;
                LDSM4(vf0, vf1, vf2, vf3, vB + rowKVb[np] + j*32 + kv_cs16);
                MMA_F16(oa[2*np],   pf[j][0], pf[j][1], pf[j][2], pf[j][3], vf0, vf1);
                MMA_F16(oa[2*np+1], pf[j][0], pf[j][1], pf[j][2], pf[j][3], vf2, vf3);
            }
        }
        __syncthreads();
    }

    // ---- epilogue (half AO) ----
    const float inv0 = 1.f / l0r, inv1 = 1.f / l1r;
    const size_t q0g = (size_t)(b*TQ + qt0 + tw + gid);
    #pragma unroll
    for (int nt = 0; nt < 8; nt++) {
        const int col = h*HD + nt*8 + tig*2;
        *(__half2*)&out[q0g*DIMN + col] = __floats2half2_rn(oa[nt][0]*inv0, oa[nt][1]*inv0);
        *(__half2*)&out[(q0g + 8)*DIMN + col] = __floats2half2_rn(oa[nt][2]*inv1, oa[nt][3]*inv1);
    }
}

// ---------------- row LayerNorm (fp32 in, half out) ----------------
__global__ __launch_bounds__(256) void ln_kernel(
    const float* __restrict__ in, const float* __restrict__ w,
    const float* __restrict__ bz, __half* __restrict__ out)
{
    const int row = blockIdx.x, tid = threadIdx.x;
    const float* xr = in + (size_t)row * DIMN;
    float4 v = ((const float4*)xr)[tid];
    float s1 = v.x + v.y + v.z + v.w;
    float s2 = v.x*v.x + v.y*v.y + v.z*v.z + v.w*v.w;
    #pragma unroll
    for (int off = 16; off; off >>= 1) {
        s1 += __shfl_xor_sync(0xffffffffu, s1, off);
        s2 += __shfl_xor_sync(0xffffffffu, s2, off);
    }
    __shared__ float sh[16];
    const int warp = tid >> 5, lane = tid & 31;
    if (lane == 0) { sh[warp] = s1; sh[8 + warp] = s2; }
    __syncthreads();
    float t1 = 0.f, t2 = 0.f;
    #pragma unroll
    for (int wi = 0; wi < 8; wi++) { t1 += sh[wi]; t2 += sh[8 + wi]; }
    const float mean = t1 * (1.0f / DIMN);
    const float var  = t2 * (1.0f / DIMN) - mean * mean;
    const float rstd = rsqrtf(var + 1e-5f);
    float4 wv = ((const float4*)w)[tid];
    float4 bv = ((const float4*)bz)[tid];
    uint2 o;
    o.x = packh2((v.x - mean)*rstd*wv.x + bv.x, (v.y - mean)*rstd*wv.y + bv.y);
    o.y = packh2((v.z - mean)*rstd*wv.z + bv.z, (v.w - mean)*rstd*wv.w + bv.w);
    *(uint2*)(out + (size_t)row * DIMN + tid*4) = o;
}

// ---------------- launcher ----------------
extern "C" void kernel_launch(void* const* d_in, const int* in_sizes, int n_in,
                              void* d_out, int out_size)
{
    const float* x    = (const float*)d_in[0];
    const float* h_a  = (const float*)d_in[1];
    const float* h_t  = (const float*)d_in[2];
    const float* p    = (const float*)d_in[3];
    const float* Wq   = (const float*)d_in[4];  const float* bq  = (const float*)d_in[5];
    const float* Wks  = (const float*)d_in[6];  const float* bks = (const float*)d_in[7];
    const float* Wvs  = (const float*)d_in[8];  const float* bvs = (const float*)d_in[9];
    const float* Wka  = (const float*)d_in[10]; const float* bka = (const float*)d_in[11];
    const float* Wva  = (const float*)d_in[12]; const float* bva = (const float*)d_in[13];
    const float* Wkt  = (const float*)d_in[14]; const float* bkt = (const float*)d_in[15];
    const float* Wvt  = (const float*)d_in[16]; const float* bvt = (const float*)d_in[17];
    const float* Wo   = (const float*)d_in[18]; const float* bo  = (const float*)d_in[19];
    const float* Wf   = (const float*)d_in[20]; const float* bf  = (const float*)d_in[21];
    const float* gating = (const float*)d_in[22];
    const float* ln_w = (const float*)d_in[23];
    const float* ln_b = (const float*)d_in[24];
    float* outp = (float*)d_out;

    __half *Qt, *Kt, *Vv, *WTb, *AOh, *LNh, *XH;
    float *Y, *RC, *RS;
    cudaGetSymbolAddress((void**)&Qt,  g_Qt);
    cudaGetSymbolAddress((void**)&Kt,  g_Kt);
    cudaGetSymbolAddress((void**)&Vv,  g_V);
    cudaGetSymbolAddress((void**)&AOh, g_AOh);
    cudaGetSymbolAddress((void**)&Y,   g_Y);
    cudaGetSymbolAddress((void**)&LNh, g_LNh);
    cudaGetSymbolAddress((void**)&RC,  g_RC);
    cudaGetSymbolAddress((void**)&RS,  g_RS);
    cudaGetSymbolAddress((void**)&WTb, g_WT);
    cudaGetSymbolAddress((void**)&XH,  g_XH);

    const size_t WSZ = (size_t)DIMN * DIMN;
    __half* WTq  = WTb + 0*WSZ;  __half* WTks = WTb + 1*WSZ;  __half* WTvs = WTb + 2*WSZ;
    __half* WTka = WTb + 3*WSZ;  __half* WTva = WTb + 4*WSZ;  __half* WTkt = WTb + 5*WSZ;
    __half* WTvt = WTb + 6*WSZ;  __half* WTo  = WTb + 7*WSZ;  __half* WTf  = WTb + 8*WSZ;

    __half* xh  = XH;                 // 4194304
    __half* hah = XH + 4194304;       // 1048576
    __half* ph  = XH + 5242880;       //  524288
    __half* hth = XH + 5767168;       //  131072

    cudaFuncSetAttribute(attn_mma, cudaFuncAttributeMaxDynamicSharedMemorySize, ATT_SMEM);

    dim3 blk(256);
    rope_tables<<<dim3(TQ/256, HD), 256>>>(RC, RS);
    W9 ws;
    ws.w[0]=Wq; ws.w[1]=Wks; ws.w[2]=Wvs; ws.w[3]=Wka; ws.w[4]=Wva;
    ws.w[5]=Wkt; ws.w[6]=Wvt; ws.w[7]=Wo; ws.w[8]=Wf;
    wtrans9<<<dim3(32, 32, 9), dim3(32, 8)>>>(ws, WTb);
    f2h<<<2048, 256>>>(x,   xh);
    f2h<<< 512, 256>>>(h_a, hah);
    f2h<<< 256, 256>>>(p,   ph);
    f2h<<<  64, 256>>>(h_t, hth);

    // projections (concat KV via toff; RoPE fused for q & k_self)
    tgemm<1,true ,false,false><<<dim3(8,32), blk>>>(xh,  WTq,  bq,  nullptr, RC, RS, Qt, 2048, TQ, 0);
    tgemm<1,true ,false,false><<<dim3(8,32), blk>>>(xh,  WTks, bks, nullptr, RC, RS, Kt, 2048, KV, 0);
    tgemm<2,false,false,false><<<dim3(8,32), blk>>>(xh,  WTvs, bvs, nullptr, nullptr, nullptr, Vv, 2048, KV, 0);
    tgemm<1,false,false,false><<<dim3(8, 8), blk>>>(hah, WTka, bka, nullptr, nullptr, nullptr, Kt,  512, KV, 2048);
    tgemm<1,false,false,false><<<dim3(8, 4), blk>>>(ph,  WTka, bka, nullptr, nullptr, nullptr, Kt,  256, KV, 2560);
    tgemm<2,false,false,false><<<dim3(8, 8), blk>>>(hah, WTva, bva, nullptr, nullptr, nullptr, Vv,  512, KV, 2048);
    tgemm<2,false,false,false><<<dim3(8, 4), blk>>>(ph,  WTva, bva, nullptr, nullptr, nullptr, Vv,  256, KV, 2560);
    tgemm<1,false,false,false><<<dim3(8, 1), blk>>>(hth, WTkt, bkt, nullptr, nullptr, nullptr, Kt,   64, KV, 2816);
    tgemm<2,false,false,false><<<dim3(8, 1), blk>>>(hth, WTvt, bvt, nullptr, nullptr, nullptr, Vv,   64, KV, 2816);

    // fp16 flash attention over concatenated KV
    attn_mma<<<dim3(TQ/128, NH, BD), dim3(256), ATT_SMEM>>>(Qt, Kt, Vv, gating, AOh);

    // out proj + residual, layernorm, FFN + relu
    tgemm<0,false,true ,false><<<dim3(8,32), blk>>>(AOh, WTo, bo, x,       nullptr, nullptr, Y,    2048, 0, 0);
    ln_kernel<<<BD*TQ, 256>>>(Y, ln_w, ln_b, LNh);
    tgemm<0,false,false,true ><<<dim3(8,32), blk>>>(LNh, WTf, bf, nullptr, nullptr, nullptr, outp, 2048, 0, 0);
}